// round 3
// baseline (speedup 1.0000x reference)
#include <cuda_runtime.h>

#define NB    5
#define BATCH 512
#define NPG   62
#define NNODES (BATCH*NPG)      /* 31744 */
#define FIN   5
#define NH    8
#define NC    3
#define EG    992               /* edges per graph */
#define NE    (BATCH*EG)        /* 507904 edges per band */
#define NEDG  (EG+NPG)          /* 1054 incl self loops */
#define DED   930

/* ---------------- device scratch (no allocations allowed) ---------------- */
__device__ float g_stats[NB][10];                 /* zero-initialized; re-zeroed by k_bnfin */
__device__ float g_bn[NB][FIN][2];                /* per-band per-feature scale/shift */
__device__ __align__(16) float g_xcat[BATCH*15];
__device__ __align__(16) float g_xout[BATCH*64];
__device__ __align__(16) float g_Q[BATCH*64];
__device__ __align__(16) float g_Kt[64*BATCH];    /* transposed K for coalesced attention */
__device__ __align__(16) float g_V[BATCH*64];

/* ================= K1a: batchnorm statistics (partial sums) ============== */
__global__ __launch_bounds__(256) void k_stats(const float* __restrict__ x)
{
    int band = blockIdx.x;
    const float* xb = x + (size_t)band * NNODES * FIN;
    float s[5] = {0,0,0,0,0}, q[5] = {0,0,0,0,0};
    for (int n = blockIdx.y * blockDim.x + threadIdx.x; n < NNODES;
         n += gridDim.y * blockDim.x) {
        const float* p = xb + (size_t)n * FIN;
        #pragma unroll
        for (int f = 0; f < 5; f++) { float v = p[f]; s[f] += v; q[f] += v*v; }
    }
    #pragma unroll
    for (int o = 16; o > 0; o >>= 1) {
        #pragma unroll
        for (int f = 0; f < 5; f++) {
            s[f] += __shfl_xor_sync(0xffffffffu, s[f], o);
            q[f] += __shfl_xor_sync(0xffffffffu, q[f], o);
        }
    }
    __shared__ float red[8][10];
    int w = threadIdx.x >> 5, lane = threadIdx.x & 31;
    if (lane == 0) {
        #pragma unroll
        for (int f = 0; f < 5; f++) { red[w][f] = s[f]; red[w][5+f] = q[f]; }
    }
    __syncthreads();
    if (threadIdx.x < 10) {
        float acc = 0.f;
        #pragma unroll
        for (int i = 0; i < 8; i++) acc += red[i][threadIdx.x];
        atomicAdd(&g_stats[band][threadIdx.x], acc);
    }
}

/* ================= K1b: finalize BN scale/shift, reset stats ============= */
__global__ void k_bnfin(const float* __restrict__ gamma, const float* __restrict__ beta)
{
    int t = threadIdx.x;                       /* 64 threads */
    if (t < NB * FIN) {
        int band = t / 5, f = t % 5;
        float ss = g_stats[band][f], qq = g_stats[band][5+f];
        float mean = ss * (1.f / NNODES);
        float var  = qq * (1.f / NNODES) - mean * mean;
        float sc   = rsqrtf(var + 1e-5f) * gamma[t];
        g_bn[band][f][0] = sc;
        g_bn[band][f][1] = beta[t] - mean * sc;
    }
    __syncthreads();
    for (int i = t; i < NB * 10; i += blockDim.x)
        ((float*)g_stats)[i] = 0.f;            /* ready for next replay */
}

/* ================= K2: per-(band,graph) GAT + pooling ==================== */
__global__ __launch_bounds__(512) void k_gat(
    const float* __restrict__ x, const int* __restrict__ ei,
    const float* __restrict__ W, const float* __restrict__ asrc,
    const float* __restrict__ adst, const float* __restrict__ gbias)
{
    int b = blockIdx.x, band = blockIdx.y;
    int t = threadIdx.x;

    __shared__ float s_xn[NPG][FIN];
    __shared__ __align__(16) float s_xt[NPG*NH*4];   /* [l][h][c0..2,pad] */
    __shared__ float s_als[NPG*NH], s_ald[NPG*NH];
    __shared__ unsigned short s_tmp[NEDG];
    __shared__ unsigned char  s_srcl[NEDG];
    __shared__ int s_cnt[64], s_scan[64], s_pos[64];
    __shared__ float s_W[FIN*24], s_as[24], s_ad[24], s_bias[NC];
    __shared__ float s_bnp[FIN][2];
    __shared__ float s_no[NPG*4];
    __shared__ float s_pool[NC];

    /* -------- phase 0: params + init -------- */
    if (t < 120)       s_W[t] = W[band*120 + t];
    else if (t < 144)  s_as[t-120] = asrc[band*24 + (t-120)];
    else if (t < 168)  s_ad[t-144] = adst[band*24 + (t-144)];
    else if (t < 171) { s_bias[t-168] = gbias[band*3 + (t-168)]; s_pool[t-168] = 0.f; }
    else if (t < 181) { int i = t-171; s_bnp[i/2][i%2] = g_bn[band][i/2][i%2]; }
    if (t < 64) s_cnt[t] = 0;
    if (t >= 200 && t < 200 + NPG*4) s_no[t-200] = 0.f;
    __syncthreads();

    /* -------- phase 1: load x + BN; stash edges + count dst -------- */
    if (t < NPG * FIN) {
        int l = t / FIN, f = t % FIN;
        float v = x[(size_t)band * NNODES * FIN + (size_t)(b*NPG + l) * FIN + f];
        s_xn[l][f] = v * s_bnp[f][0] + s_bnp[f][1];
    }
    {
        const int* sp = ei + (size_t)band * 2 * NE + (size_t)b * EG;
        const int* dp = sp + NE;
        int base = b * NPG;
        for (int e = t; e < NEDG; e += 512) {
            int ls, ld;
            if (e < EG) { ls = sp[e] - base; ld = dp[e] - base; }
            else        { ls = ld = e - EG; }                 /* self loops */
            s_tmp[e] = (unsigned short)(ls | (ld << 8));
            atomicAdd(&s_cnt[ld], 1);
        }
    }
    __syncthreads();

    /* -------- phase 2: xt = xn @ W  (5 -> 24) -------- */
    for (int idx = t; idx < NPG * 24; idx += 512) {
        int l = idx / 24, k = idx % 24;
        float acc = s_xn[l][0]*s_W[k]      + s_xn[l][1]*s_W[24+k]
                  + s_xn[l][2]*s_W[48+k]   + s_xn[l][3]*s_W[72+k]
                  + s_xn[l][4]*s_W[96+k];
        int h = k / 3, c = k % 3;
        s_xt[l*32 + h*4 + c] = acc;
    }

    /* inclusive scan over 64 counters (Hillis-Steele) */
    if (t < 64) s_scan[t] = s_cnt[t];
    __syncthreads();
    #pragma unroll
    for (int off = 1; off < 64; off <<= 1) {
        int v = 0;
        if (t < 64 && t >= off) v = s_scan[t - off];
        __syncthreads();
        if (t < 64) s_scan[t] += v;
        __syncthreads();
    }
    if (t < 64) s_pos[t] = s_scan[t] - s_cnt[t];

    /* attention logit halves per node/head */
    for (int idx = t; idx < NPG * NH; idx += 512) {
        int l = idx >> 3, h = idx & 7;
        const float* xp = &s_xt[l*32 + h*4];
        s_als[idx] = xp[0]*s_as[h*3] + xp[1]*s_as[h*3+1] + xp[2]*s_as[h*3+2];
        s_ald[idx] = xp[0]*s_ad[h*3] + xp[1]*s_ad[h*3+1] + xp[2]*s_ad[h*3+2];
    }
    __syncthreads();

    /* -------- phase 3: counting-sort scatter into CSR -------- */
    for (int e = t; e < NEDG; e += 512) {
        unsigned u = s_tmp[e];
        int ld = u >> 8;
        int p = atomicAdd(&s_pos[ld], 1);
        s_srcl[p] = (unsigned char)(u & 0xFF);
    }
    __syncthreads();

    /* -------- phase 4: atomic-free gather per (dst, head) -------- */
    if (t < NPG * NH) {
        int d = t >> 3, h = t & 7;
        int end = s_scan[d];
        int beg = end - s_cnt[d];
        float ald = s_ald[t];
        float den = 0.f, a0 = 0.f, a1 = 0.f, a2 = 0.f;
        for (int e = beg; e < end; e++) {
            int ls = s_srcl[e];
            float ev = s_als[ls*8 + h] + ald;
            ev = ev > 0.f ? ev : 0.2f * ev;                /* leaky 0.2 */
            float wgt = __expf(ev);                        /* no max-sub: |ev| small */
            const float4 xv = *(const float4*)&s_xt[ls*32 + h*4];
            den += wgt; a0 += wgt*xv.x; a1 += wgt*xv.y; a2 += wgt*xv.z;
        }
        float inv = 0.125f / den;                          /* /denom then head-mean */
        atomicAdd(&s_no[d*4+0], a0*inv);
        atomicAdd(&s_no[d*4+1], a1*inv);
        atomicAdd(&s_no[d*4+2], a2*inv);
    }
    __syncthreads();

    /* -------- phase 5: bias + elu + graph mean-pool -------- */
    if (t < NPG * NC) {
        int d = t / 3, c = t % 3;
        float v = s_no[d*4+c] + s_bias[c];
        v = v > 0.f ? v : expm1f(v);
        atomicAdd(&s_pool[c], v);
    }
    __syncthreads();
    if (t < NC) g_xcat[b*15 + band*3 + t] = s_pool[t] * (1.f/62.f);
}

/* ====== K3: LayerNorm + QKV projections + fg branch (8 rows/block) ====== */
__global__ __launch_bounds__(256) void k_qkv(
    const float* __restrict__ de, const float* __restrict__ lng,
    const float* __restrict__ lnb,
    const float* __restrict__ qW, const float* __restrict__ qb,
    const float* __restrict__ kW, const float* __restrict__ kb,
    const float* __restrict__ vW, const float* __restrict__ vb,
    const float* __restrict__ fgW, const float* __restrict__ fgb)
{
    __shared__ float s_n[8][DED];
    int w = threadIdx.x >> 5, lane = threadIdx.x & 31;
    int row = blockIdx.x * 8 + w;
    const float* dr = de + (size_t)row * DED;

    float ssum = 0.f, ssq = 0.f;
    for (int j = lane; j < DED; j += 32) {
        float v = dr[j]; s_n[w][j] = v; ssum += v; ssq += v*v;
    }
    #pragma unroll
    for (int o = 16; o > 0; o >>= 1) {
        ssum += __shfl_xor_sync(0xffffffffu, ssum, o);
        ssq  += __shfl_xor_sync(0xffffffffu, ssq, o);
    }
    float mu   = ssum * (1.f/DED);
    float rstd = rsqrtf(ssq * (1.f/DED) - mu*mu + 1e-5f);
    __syncwarp();
    for (int j = lane; j < DED; j += 32)
        s_n[w][j] = (s_n[w][j] - mu) * rstd * lng[j] + lnb[j];
    __syncwarp();

    if (blockIdx.y == 0) {
        /* Q (lanes 0-15) and K (lanes 16-31): each lane 4 consecutive cols */
        const float* Wsel = (lane < 16) ? qW : kW;
        const float* bsel = (lane < 16) ? qb : kb;
        int jj = (lane * 4) & 63;
        const float* wp = Wsel + jj;
        float a0 = 0.f, a1 = 0.f, a2 = 0.f, a3 = 0.f;
        #pragma unroll 4
        for (int i = 0; i < DED; i++) {
            float4 wv = *(const float4*)(wp + i*64);
            float a = s_n[w][i];
            a0 += a*wv.x; a1 += a*wv.y; a2 += a*wv.z; a3 += a*wv.w;
        }
        a0 += bsel[jj]; a1 += bsel[jj+1]; a2 += bsel[jj+2]; a3 += bsel[jj+3];
        if (lane < 16) {
            *(float4*)&g_Q[row*64 + jj] = make_float4(a0, a1, a2, a3);
        } else {
            g_Kt[(jj+0)*BATCH + row] = a0; g_Kt[(jj+1)*BATCH + row] = a1;
            g_Kt[(jj+2)*BATCH + row] = a2; g_Kt[(jj+3)*BATCH + row] = a3;
        }
    } else {
        if (lane < 16) {
            /* V */
            int jj = lane * 4;
            const float* wp = vW + jj;
            float a0 = 0.f, a1 = 0.f, a2 = 0.f, a3 = 0.f;
            #pragma unroll 4
            for (int i = 0; i < DED; i++) {
                float4 wv = *(const float4*)(wp + i*64);
                float a = s_n[w][i];
                a0 += a*wv.x; a1 += a*wv.y; a2 += a*wv.z; a3 += a*wv.w;
            }
            a0 += vb[jj]; a1 += vb[jj+1]; a2 += vb[jj+2]; a3 += vb[jj+3];
            *(float4*)&g_V[row*64 + jj] = make_float4(a0, a1, a2, a3);
        } else {
            /* x_out = elu(xcat @ fgW + fgb) */
            int j = (lane - 16) * 4;
            float a0 = fgb[j], a1 = fgb[j+1], a2 = fgb[j+2], a3 = fgb[j+3];
            #pragma unroll
            for (int i = 0; i < 15; i++) {
                float xc = g_xcat[row*15 + i];
                float4 wv = *(const float4*)(fgW + i*64 + j);
                a0 += xc*wv.x; a1 += xc*wv.y; a2 += xc*wv.z; a3 += xc*wv.w;
            }
            a0 = a0 > 0.f ? a0 : expm1f(a0);
            a1 = a1 > 0.f ? a1 : expm1f(a1);
            a2 = a2 > 0.f ? a2 : expm1f(a2);
            a3 = a3 > 0.f ? a3 : expm1f(a3);
            *(float4*)&g_xout[row*64 + j] = make_float4(a0, a1, a2, a3);
        }
    }
}

/* ====== K4: 512x512 attention + final FC + elu (4 Q rows / block) ======= */
__global__ __launch_bounds__(256) void k_attn(
    float* __restrict__ out, const float* __restrict__ faW,
    const float* __restrict__ fab)
{
    __shared__ float s_q[4*64], s_xo[4*64], s_sc[4*512], s_de[4*64];
    __shared__ float s_part[8][4];
    __shared__ float s_inv[4];
    int t = threadIdx.x, rowbase = blockIdx.x * 4;

    { int r = t >> 6, c = t & 63;
      s_q[t]  = g_Q[(rowbase+r)*64 + c];
      s_xo[t] = g_xout[(rowbase+r)*64 + c]; }
    __syncthreads();

    /* scores + exp + partial row sums */
    float ps[4];
    {
        int j0 = t, j1 = t + 256;
        float acc[4][2] = {};
        #pragma unroll 8
        for (int c = 0; c < 64; c++) {
            float k0 = g_Kt[c*BATCH + j0], k1 = g_Kt[c*BATCH + j1];
            #pragma unroll
            for (int r = 0; r < 4; r++) {
                float qv = s_q[r*64 + c];
                acc[r][0] += qv * k0; acc[r][1] += qv * k1;
            }
        }
        #pragma unroll
        for (int r = 0; r < 4; r++) {
            float p0 = __expf(acc[r][0] * 0.125f);
            float p1 = __expf(acc[r][1] * 0.125f);
            s_sc[r*512 + j0] = p0; s_sc[r*512 + j1] = p1;
            ps[r] = p0 + p1;
        }
    }
    #pragma unroll
    for (int o = 16; o > 0; o >>= 1) {
        #pragma unroll
        for (int r = 0; r < 4; r++) ps[r] += __shfl_xor_sync(0xffffffffu, ps[r], o);
    }
    { int w = t >> 5, lane = t & 31;
      if (lane == 0) { s_part[w][0]=ps[0]; s_part[w][1]=ps[1]; s_part[w][2]=ps[2]; s_part[w][3]=ps[3]; } }
    __syncthreads();
    if (t < 4) {
        float s = 0.f;
        #pragma unroll
        for (int w = 0; w < 8; w++) s += s_part[w][t];
        s_inv[t] = 1.f / s;
    }
    __syncthreads();

    /* x_de = (P @ V) * inv */
    {
        int r = t >> 6, c = t & 63;
        const float* vp = g_V + c;
        const float* pp = &s_sc[r*512];
        float b0=0.f, b1=0.f, b2=0.f, b3=0.f;
        for (int j = 0; j < 512; j += 4) {
            b0 += pp[j]   * vp[(j)  *64];
            b1 += pp[j+1] * vp[(j+1)*64];
            b2 += pp[j+2] * vp[(j+2)*64];
            b3 += pp[j+3] * vp[(j+3)*64];
        }
        s_de[t] = ((b0+b1)+(b2+b3)) * s_inv[r];
    }
    __syncthreads();

    /* final: elu([x_out | x_de] @ faW + fab) */
    if (t < 12) {
        int r = t / 3, c = t % 3;
        float acc = fab[c];
        #pragma unroll 8
        for (int i = 0; i < 64; i++) {
            acc += s_xo[r*64 + i] * faW[i*3 + c];
            acc += s_de[r*64 + i] * faW[(64+i)*3 + c];
        }
        acc = acc > 0.f ? acc : expm1f(acc);
        out[(rowbase+r)*3 + c] = acc;
    }
}

/* ============================== launcher ================================ */
extern "C" void kernel_launch(void* const* d_in, const int* in_sizes, int n_in,
                              void* d_out, int out_size)
{
    const float* x     = (const float*)d_in[0];
    const int*   ei    = (const int*)  d_in[1];
    /* d_in[2] = batch (implied by structure) */
    const float* de    = (const float*)d_in[3];
    const float* bng   = (const float*)d_in[4];
    const float* bnb   = (const float*)d_in[5];
    const float* W     = (const float*)d_in[6];
    const float* asrc  = (const float*)d_in[7];
    const float* adst  = (const float*)d_in[8];
    const float* gbias = (const float*)d_in[9];
    const float* fgW   = (const float*)d_in[10];
    const float* fgb   = (const float*)d_in[11];
    const float* lng   = (const float*)d_in[12];
    const float* lnb   = (const float*)d_in[13];
    const float* qW    = (const float*)d_in[14];
    const float* qb    = (const float*)d_in[15];
    const float* kW    = (const float*)d_in[16];
    const float* kb    = (const float*)d_in[17];
    const float* vW    = (const float*)d_in[18];
    const float* vb    = (const float*)d_in[19];
    const float* faW   = (const float*)d_in[20];
    const float* fab   = (const float*)d_in[21];
    float* out = (float*)d_out;

    k_stats<<<dim3(NB, 24), 256>>>(x);
    k_bnfin<<<1, 64>>>(bng, bnb);
    k_gat<<<dim3(BATCH, NB), 512>>>(x, ei, W, asrc, adst, gbias);
    k_qkv<<<dim3(64, 2), 256>>>(de, lng, lnb, qW, qb, kW, kb, vW, vb, fgW, fgb);
    k_attn<<<128, 256>>>(out, faW, fab);
}

// round 4
// speedup vs baseline: 1.3192x; 1.3192x over previous
#include <cuda_runtime.h>

#define NB    5
#define BATCH 512
#define NPG   62
#define NNODES (BATCH*NPG)      /* 31744 */
#define FIN   5
#define NH    8
#define NC    3
#define EG    992               /* edges per graph */
#define NE    (BATCH*EG)        /* 507904 edges per band */
#define NEDG  (EG+NPG)          /* 1054 incl self loops */
#define DED   930

/* ---------------- device scratch (no allocations allowed) ---------------- */
__device__ float g_stats[NB][10];                 /* zero-init; re-zeroed by k_bnfin */
__device__ float g_bn[NB][FIN][2];
__device__ __align__(16) float g_xcat[BATCH*15];
__device__ __align__(16) float g_xout[BATCH*64];
__device__ __align__(16) float g_Q[BATCH*64];
__device__ __align__(16) float g_Kt[64*BATCH];    /* transposed K */
__device__ __align__(16) float g_V[BATCH*64];
__device__ __align__(16) float g_den[BATCH*DED];  /* layernormed de */

/* ================= K1a: batchnorm statistics (partial sums) ============== */
__global__ __launch_bounds__(256) void k_stats(const float* __restrict__ x)
{
    int band = blockIdx.x;
    const float* xb = x + (size_t)band * NNODES * FIN;
    float s[5] = {0,0,0,0,0}, q[5] = {0,0,0,0,0};
    for (int n = blockIdx.y * blockDim.x + threadIdx.x; n < NNODES;
         n += gridDim.y * blockDim.x) {
        const float* p = xb + (size_t)n * FIN;
        #pragma unroll
        for (int f = 0; f < 5; f++) { float v = p[f]; s[f] += v; q[f] += v*v; }
    }
    #pragma unroll
    for (int o = 16; o > 0; o >>= 1) {
        #pragma unroll
        for (int f = 0; f < 5; f++) {
            s[f] += __shfl_xor_sync(0xffffffffu, s[f], o);
            q[f] += __shfl_xor_sync(0xffffffffu, q[f], o);
        }
    }
    __shared__ float red[8][10];
    int w = threadIdx.x >> 5, lane = threadIdx.x & 31;
    if (lane == 0) {
        #pragma unroll
        for (int f = 0; f < 5; f++) { red[w][f] = s[f]; red[w][5+f] = q[f]; }
    }
    __syncthreads();
    if (threadIdx.x < 10) {
        float acc = 0.f;
        #pragma unroll
        for (int i = 0; i < 8; i++) acc += red[i][threadIdx.x];
        atomicAdd(&g_stats[band][threadIdx.x], acc);
    }
}

/* ================= K1b: finalize BN scale/shift, reset stats ============= */
__global__ void k_bnfin(const float* __restrict__ gamma, const float* __restrict__ beta)
{
    int t = threadIdx.x;                       /* 64 threads */
    if (t < NB * FIN) {
        int band = t / 5, f = t % 5;
        float ss = g_stats[band][f], qq = g_stats[band][5+f];
        float mean = ss * (1.f / NNODES);
        float var  = qq * (1.f / NNODES) - mean * mean;
        float sc   = rsqrtf(var + 1e-5f) * gamma[t];
        g_bn[band][f][0] = sc;
        g_bn[band][f][1] = beta[t] - mean * sc;
    }
    __syncthreads();
    for (int i = t; i < NB * 10; i += blockDim.x)
        ((float*)g_stats)[i] = 0.f;            /* ready for next replay */
}

/* ================= K2: per-(band,graph) GAT + pooling ==================== */
__global__ __launch_bounds__(512) void k_gat(
    const float* __restrict__ x, const int* __restrict__ ei,
    const float* __restrict__ W, const float* __restrict__ asrc,
    const float* __restrict__ adst, const float* __restrict__ gbias)
{
    int b = blockIdx.x, band = blockIdx.y;
    int t = threadIdx.x;

    __shared__ float s_xn[NPG][FIN];
    __shared__ __align__(16) float s_xt[NPG*NH*4];
    __shared__ float s_als[NPG*NH], s_ald[NPG*NH];
    __shared__ unsigned short s_tmp[NEDG];
    __shared__ unsigned char  s_srcl[NEDG];
    __shared__ int s_cnt[64], s_scan[64], s_pos[64];
    __shared__ float s_W[FIN*24], s_as[24], s_ad[24], s_bias[NC];
    __shared__ float s_bnp[FIN][2];
    __shared__ float s_no[NPG*4];
    __shared__ float s_pool[NC];

    if (t < 120)       s_W[t] = W[band*120 + t];
    else if (t < 144)  s_as[t-120] = asrc[band*24 + (t-120)];
    else if (t < 168)  s_ad[t-144] = adst[band*24 + (t-144)];
    else if (t < 171) { s_bias[t-168] = gbias[band*3 + (t-168)]; s_pool[t-168] = 0.f; }
    else if (t < 181) { int i = t-171; s_bnp[i/2][i%2] = g_bn[band][i/2][i%2]; }
    if (t < 64) s_cnt[t] = 0;
    if (t >= 200 && t < 200 + NPG*4) s_no[t-200] = 0.f;
    __syncthreads();

    if (t < NPG * FIN) {
        int l = t / FIN, f = t % FIN;
        float v = x[(size_t)band * NNODES * FIN + (size_t)(b*NPG + l) * FIN + f];
        s_xn[l][f] = v * s_bnp[f][0] + s_bnp[f][1];
    }
    {
        const int* sp = ei + (size_t)band * 2 * NE + (size_t)b * EG;
        const int* dp = sp + NE;
        int base = b * NPG;
        for (int e = t; e < NEDG; e += 512) {
            int ls, ld;
            if (e < EG) { ls = sp[e] - base; ld = dp[e] - base; }
            else        { ls = ld = e - EG; }
            s_tmp[e] = (unsigned short)(ls | (ld << 8));
            atomicAdd(&s_cnt[ld], 1);
        }
    }
    __syncthreads();

    for (int idx = t; idx < NPG * 24; idx += 512) {
        int l = idx / 24, k = idx % 24;
        float acc = s_xn[l][0]*s_W[k]      + s_xn[l][1]*s_W[24+k]
                  + s_xn[l][2]*s_W[48+k]   + s_xn[l][3]*s_W[72+k]
                  + s_xn[l][4]*s_W[96+k];
        int h = k / 3, c = k % 3;
        s_xt[l*32 + h*4 + c] = acc;
    }

    if (t < 64) s_scan[t] = s_cnt[t];
    __syncthreads();
    #pragma unroll
    for (int off = 1; off < 64; off <<= 1) {
        int v = 0;
        if (t < 64 && t >= off) v = s_scan[t - off];
        __syncthreads();
        if (t < 64) s_scan[t] += v;
        __syncthreads();
    }
    if (t < 64) s_pos[t] = s_scan[t] - s_cnt[t];

    for (int idx = t; idx < NPG * NH; idx += 512) {
        int l = idx >> 3, h = idx & 7;
        const float* xp = &s_xt[l*32 + h*4];
        s_als[idx] = xp[0]*s_as[h*3] + xp[1]*s_as[h*3+1] + xp[2]*s_as[h*3+2];
        s_ald[idx] = xp[0]*s_ad[h*3] + xp[1]*s_ad[h*3+1] + xp[2]*s_ad[h*3+2];
    }
    __syncthreads();

    for (int e = t; e < NEDG; e += 512) {
        unsigned u = s_tmp[e];
        int ld = u >> 8;
        int p = atomicAdd(&s_pos[ld], 1);
        s_srcl[p] = (unsigned char)(u & 0xFF);
    }
    __syncthreads();

    if (t < NPG * NH) {
        int d = t >> 3, h = t & 7;
        int end = s_scan[d];
        int beg = end - s_cnt[d];
        float ald = s_ald[t];
        float den = 0.f, a0 = 0.f, a1 = 0.f, a2 = 0.f;
        for (int e = beg; e < end; e++) {
            int ls = s_srcl[e];
            float ev = s_als[ls*8 + h] + ald;
            ev = ev > 0.f ? ev : 0.2f * ev;
            float wgt = __expf(ev);
            const float4 xv = *(const float4*)&s_xt[ls*32 + h*4];
            den += wgt; a0 += wgt*xv.x; a1 += wgt*xv.y; a2 += wgt*xv.z;
        }
        float inv = 0.125f / den;
        atomicAdd(&s_no[d*4+0], a0*inv);
        atomicAdd(&s_no[d*4+1], a1*inv);
        atomicAdd(&s_no[d*4+2], a2*inv);
    }
    __syncthreads();

    if (t < NPG * NC) {
        int d = t / 3, c = t % 3;
        float v = s_no[d*4+c] + s_bias[c];
        v = v > 0.f ? v : expm1f(v);
        atomicAdd(&s_pool[c], v);
    }
    __syncthreads();
    if (t < NC) g_xcat[b*15 + band*3 + t] = s_pool[t] * (1.f/62.f);
}

/* ================= K3a: LayerNorm (warp per row) ========================= */
__global__ __launch_bounds__(128) void k_ln(
    const float* __restrict__ de, const float* __restrict__ lng,
    const float* __restrict__ lnb)
{
    int w = threadIdx.x >> 5, lane = threadIdx.x & 31;
    int row = blockIdx.x * 4 + w;
    const float* dr = de + (size_t)row * DED;
    float v[30];
    float ssum = 0.f, ssq = 0.f;
    #pragma unroll
    for (int i = 0; i < 30; i++) {
        int j = lane + i*32;
        float z = (j < DED) ? dr[j] : 0.f;
        v[i] = z; ssum += z; ssq += z*z;
    }
    #pragma unroll
    for (int o = 16; o > 0; o >>= 1) {
        ssum += __shfl_xor_sync(0xffffffffu, ssum, o);
        ssq  += __shfl_xor_sync(0xffffffffu, ssq, o);
    }
    float mu   = ssum * (1.f/DED);
    float rstd = rsqrtf(ssq * (1.f/DED) - mu*mu + 1e-5f);
    float* out = g_den + (size_t)row * DED;
    #pragma unroll
    for (int i = 0; i < 30; i++) {
        int j = lane + i*32;
        if (j < DED) out[j] = (v[i] - mu) * rstd * lng[j] + lnb[j];
    }
}

/* ===== K3b: QKV GEMM [512,930]@[930,64], 16-row tiles, 4x4 reg tiles ===== */
#define KT 32
__global__ __launch_bounds__(64) void k_gemm(
    const float* __restrict__ qW, const float* __restrict__ qb,
    const float* __restrict__ kW, const float* __restrict__ kb,
    const float* __restrict__ vW, const float* __restrict__ vb)
{
    int mat = blockIdx.y;
    const float* Wm = (mat == 0) ? qW : (mat == 1) ? kW : vW;
    const float* bm = (mat == 0) ? qb : (mat == 1) ? kb : vb;
    int row0 = blockIdx.x * 16;
    int t = threadIdx.x;
    int cg = t & 15;           /* col group: cols cg*4 .. +3 */
    int rg = t >> 4;           /* row group: rows rg*4 .. +3 */

    __shared__ __align__(16) float sA[KT][20];   /* [k][row], padded */
    __shared__ __align__(16) float sW[KT][64];

    float acc[4][4] = {};

    for (int kc = 0; kc < 30; kc++) {
        int k0 = kc * KT;
        /* A tile: 16 rows x 32 k, coalesced read, transposed store */
        #pragma unroll
        for (int idx = t; idx < 16*KT; idx += 64) {
            int r = idx >> 5, kk = idx & 31;
            int k = k0 + kk;
            sA[kk][r] = (k < DED) ? g_den[(size_t)(row0 + r) * DED + k] : 0.f;
        }
        /* W tile: 32 k x 64 cols, float4 coalesced */
        #pragma unroll
        for (int idx = t; idx < 512; idx += 64) {
            int kk = idx >> 4, c4 = idx & 15;
            int k = k0 + kk;
            float4 wv = (k < DED) ? *(const float4*)(Wm + (size_t)k*64 + c4*4)
                                  : make_float4(0.f,0.f,0.f,0.f);
            *(float4*)&sW[kk][c4*4] = wv;
        }
        __syncthreads();
        #pragma unroll
        for (int kk = 0; kk < KT; kk++) {
            float4 a = *(const float4*)&sA[kk][rg*4];
            float4 w = *(const float4*)&sW[kk][cg*4];
            acc[0][0] += a.x*w.x; acc[0][1] += a.x*w.y; acc[0][2] += a.x*w.z; acc[0][3] += a.x*w.w;
            acc[1][0] += a.y*w.x; acc[1][1] += a.y*w.y; acc[1][2] += a.y*w.z; acc[1][3] += a.y*w.w;
            acc[2][0] += a.z*w.x; acc[2][1] += a.z*w.y; acc[2][2] += a.z*w.z; acc[2][3] += a.z*w.w;
            acc[3][0] += a.w*w.x; acc[3][1] += a.w*w.y; acc[3][2] += a.w*w.z; acc[3][3] += a.w*w.w;
        }
        __syncthreads();
    }

    float b0 = bm[cg*4], b1 = bm[cg*4+1], b2 = bm[cg*4+2], b3 = bm[cg*4+3];
    if (mat == 1) {
        /* K: transposed store, float4 down the row dimension */
        #pragma unroll
        for (int j = 0; j < 4; j++) {
            int c = cg*4 + j;
            float bb = bm[c];
            *(float4*)&g_Kt[(size_t)c*BATCH + row0 + rg*4] =
                make_float4(acc[0][j]+bb, acc[1][j]+bb, acc[2][j]+bb, acc[3][j]+bb);
        }
    } else {
        float* dst = (mat == 0) ? g_Q : g_V;
        #pragma unroll
        for (int i = 0; i < 4; i++) {
            *(float4*)&dst[(size_t)(row0 + rg*4 + i)*64 + cg*4] =
                make_float4(acc[i][0]+b0, acc[i][1]+b1, acc[i][2]+b2, acc[i][3]+b3);
        }
    }
}

/* ============== K3c: x_out = elu(xcat @ fgW + fgb), tiny FC ============== */
__global__ __launch_bounds__(512) void k_fg(
    const float* __restrict__ fgW, const float* __restrict__ fgb)
{
    int t = threadIdx.x;
    int row = blockIdx.x * 8 + (t >> 6);
    int col = t & 63;
    float acc = fgb[col];
    #pragma unroll
    for (int i = 0; i < 15; i++)
        acc += g_xcat[row*15 + i] * fgW[i*64 + col];
    acc = acc > 0.f ? acc : expm1f(acc);
    g_xout[row*64 + col] = acc;
}

/* ====== K4: 512x512 attention + final FC + elu (4 Q rows / block) ======= */
__global__ __launch_bounds__(256) void k_attn(
    float* __restrict__ out, const float* __restrict__ faW,
    const float* __restrict__ fab)
{
    __shared__ float s_q[4*64], s_xo[4*64], s_sc[4*512], s_de[4*64];
    __shared__ float s_part[8][4];
    __shared__ float s_inv[4];
    int t = threadIdx.x, rowbase = blockIdx.x * 4;

    { int r = t >> 6, c = t & 63;
      s_q[t]  = g_Q[(rowbase+r)*64 + c];
      s_xo[t] = g_xout[(rowbase+r)*64 + c]; }
    __syncthreads();

    float ps[4];
    {
        int j0 = t, j1 = t + 256;
        float acc[4][2] = {};
        #pragma unroll 8
        for (int c = 0; c < 64; c++) {
            float k0 = g_Kt[c*BATCH + j0], k1 = g_Kt[c*BATCH + j1];
            #pragma unroll
            for (int r = 0; r < 4; r++) {
                float qv = s_q[r*64 + c];
                acc[r][0] += qv * k0; acc[r][1] += qv * k1;
            }
        }
        #pragma unroll
        for (int r = 0; r < 4; r++) {
            float p0 = __expf(acc[r][0] * 0.125f);
            float p1 = __expf(acc[r][1] * 0.125f);
            s_sc[r*512 + j0] = p0; s_sc[r*512 + j1] = p1;
            ps[r] = p0 + p1;
        }
    }
    #pragma unroll
    for (int o = 16; o > 0; o >>= 1) {
        #pragma unroll
        for (int r = 0; r < 4; r++) ps[r] += __shfl_xor_sync(0xffffffffu, ps[r], o);
    }
    { int w = t >> 5, lane = t & 31;
      if (lane == 0) { s_part[w][0]=ps[0]; s_part[w][1]=ps[1]; s_part[w][2]=ps[2]; s_part[w][3]=ps[3]; } }
    __syncthreads();
    if (t < 4) {
        float s = 0.f;
        #pragma unroll
        for (int w = 0; w < 8; w++) s += s_part[w][t];
        s_inv[t] = 1.f / s;
    }
    __syncthreads();

    {
        int r = t >> 6, c = t & 63;
        const float* vp = g_V + c;
        const float* pp = &s_sc[r*512];
        float b0=0.f, b1=0.f, b2=0.f, b3=0.f;
        for (int j = 0; j < 512; j += 4) {
            b0 += pp[j]   * vp[(j)  *64];
            b1 += pp[j+1] * vp[(j+1)*64];
            b2 += pp[j+2] * vp[(j+2)*64];
            b3 += pp[j+3] * vp[(j+3)*64];
        }
        s_de[t] = ((b0+b1)+(b2+b3)) * s_inv[r];
    }
    __syncthreads();

    if (t < 12) {
        int r = t / 3, c = t % 3;
        float acc = fab[c];
        #pragma unroll 8
        for (int i = 0; i < 64; i++) {
            acc += s_xo[r*64 + i] * faW[i*3 + c];
            acc += s_de[r*64 + i] * faW[(64+i)*3 + c];
        }
        acc = acc > 0.f ? acc : expm1f(acc);
        out[(rowbase+r)*3 + c] = acc;
    }
}

/* ============================== launcher ================================ */
extern "C" void kernel_launch(void* const* d_in, const int* in_sizes, int n_in,
                              void* d_out, int out_size)
{
    const float* x     = (const float*)d_in[0];
    const int*   ei    = (const int*)  d_in[1];
    const float* de    = (const float*)d_in[3];
    const float* bng   = (const float*)d_in[4];
    const float* bnb   = (const float*)d_in[5];
    const float* W     = (const float*)d_in[6];
    const float* asrc  = (const float*)d_in[7];
    const float* adst  = (const float*)d_in[8];
    const float* gbias = (const float*)d_in[9];
    const float* fgW   = (const float*)d_in[10];
    const float* fgb   = (const float*)d_in[11];
    const float* lng   = (const float*)d_in[12];
    const float* lnb   = (const float*)d_in[13];
    const float* qW    = (const float*)d_in[14];
    const float* qb    = (const float*)d_in[15];
    const float* kW    = (const float*)d_in[16];
    const float* kb    = (const float*)d_in[17];
    const float* vW    = (const float*)d_in[18];
    const float* vb    = (const float*)d_in[19];
    const float* faW   = (const float*)d_in[20];
    const float* fab   = (const float*)d_in[21];
    float* out = (float*)d_out;

    k_ln<<<128, 128>>>(de, lng, lnb);
    k_stats<<<dim3(NB, 24), 256>>>(x);
    k_bnfin<<<1, 64>>>(bng, bnb);
    k_gemm<<<dim3(32, 3), 64>>>(qW, qb, kW, kb, vW, vb);
    k_gat<<<dim3(BATCH, NB), 512>>>(x, ei, W, asrc, adst, gbias);
    k_fg<<<64, 512>>>(fgW, fgb);
    k_attn<<<128, 256>>>(out, faW, fab);
}

// round 5
// speedup vs baseline: 1.4532x; 1.1016x over previous
#include <cuda_runtime.h>

#define NB    5
#define BATCH 512
#define NPG   62
#define NNODES (BATCH*NPG)      /* 31744 */
#define FIN   5
#define NH    8
#define NC    3
#define EG    992               /* edges per graph */
#define NE    (BATCH*EG)        /* 507904 edges per band */
#define NEDG  (EG+NPG)          /* 1054 incl self loops */
#define DED   930

/* ---------------- device scratch (no allocations allowed) ---------------- */
__device__ float g_stats[NB][10];                 /* zero-init; re-zeroed by k_bnfin */
__device__ float g_bn[NB][FIN][2];
__device__ __align__(16) float g_xcat[BATCH*15];
__device__ __align__(16) float g_Q[BATCH*64];
__device__ __align__(16) float g_Kt[64*BATCH];    /* transposed K */
__device__ __align__(16) float g_V[BATCH*64];
__device__ __align__(16) float g_den[BATCH*DED];  /* layernormed de */

/* ========== K1: fused BN-stats (blocks 0..119) + LayerNorm (120..183) ==== */
__global__ __launch_bounds__(256) void k_pre(
    const float* __restrict__ x, const float* __restrict__ de,
    const float* __restrict__ lng, const float* __restrict__ lnb)
{
    if (blockIdx.x < 120) {
        /* BN statistics: band = bx/24, slice = bx%24 */
        int band = blockIdx.x / 24, slice = blockIdx.x % 24;
        const float* xb = x + (size_t)band * NNODES * FIN;
        float s[5] = {0,0,0,0,0}, q[5] = {0,0,0,0,0};
        for (int n = slice * 256 + threadIdx.x; n < NNODES; n += 24 * 256) {
            const float* p = xb + (size_t)n * FIN;
            #pragma unroll
            for (int f = 0; f < 5; f++) { float v = p[f]; s[f] += v; q[f] += v*v; }
        }
        #pragma unroll
        for (int o = 16; o > 0; o >>= 1) {
            #pragma unroll
            for (int f = 0; f < 5; f++) {
                s[f] += __shfl_xor_sync(0xffffffffu, s[f], o);
                q[f] += __shfl_xor_sync(0xffffffffu, q[f], o);
            }
        }
        __shared__ float red[8][10];
        int w = threadIdx.x >> 5, lane = threadIdx.x & 31;
        if (lane == 0) {
            #pragma unroll
            for (int f = 0; f < 5; f++) { red[w][f] = s[f]; red[w][5+f] = q[f]; }
        }
        __syncthreads();
        if (threadIdx.x < 10) {
            float acc = 0.f;
            #pragma unroll
            for (int i = 0; i < 8; i++) acc += red[i][threadIdx.x];
            atomicAdd(&g_stats[band][threadIdx.x], acc);
        }
    } else {
        /* LayerNorm: warp per row, 8 rows per block */
        int blk = blockIdx.x - 120;
        int w = threadIdx.x >> 5, lane = threadIdx.x & 31;
        int row = blk * 8 + w;
        const float* dr = de + (size_t)row * DED;
        float v[30];
        float ssum = 0.f, ssq = 0.f;
        #pragma unroll
        for (int i = 0; i < 30; i++) {
            int j = lane + i*32;
            float z = (j < DED) ? dr[j] : 0.f;
            v[i] = z; ssum += z; ssq += z*z;
        }
        #pragma unroll
        for (int o = 16; o > 0; o >>= 1) {
            ssum += __shfl_xor_sync(0xffffffffu, ssum, o);
            ssq  += __shfl_xor_sync(0xffffffffu, ssq, o);
        }
        float mu   = ssum * (1.f/DED);
        float rstd = rsqrtf(ssq * (1.f/DED) - mu*mu + 1e-5f);
        float* outp = g_den + (size_t)row * DED;
        #pragma unroll
        for (int i = 0; i < 30; i++) {
            int j = lane + i*32;
            if (j < DED) outp[j] = (v[i] - mu) * rstd * lng[j] + lnb[j];
        }
    }
}

/* ================= K1b: finalize BN scale/shift, reset stats ============= */
__global__ void k_bnfin(const float* __restrict__ gamma, const float* __restrict__ beta)
{
    int t = threadIdx.x;                       /* 64 threads */
    if (t < NB * FIN) {
        int band = t / 5, f = t % 5;
        float ss = g_stats[band][f], qq = g_stats[band][5+f];
        float mean = ss * (1.f / NNODES);
        float var  = qq * (1.f / NNODES) - mean * mean;
        float sc   = rsqrtf(var + 1e-5f) * gamma[t];
        g_bn[band][f][0] = sc;
        g_bn[band][f][1] = beta[t] - mean * sc;
    }
    __syncthreads();
    for (int i = t; i < NB * 10; i += blockDim.x)
        ((float*)g_stats)[i] = 0.f;            /* ready for next replay */
}

/* ===== K2: QKV GEMM [512,930]@[930,64], 8-row tiles, 4-way split-K ====== */
#define GKT 16
__global__ __launch_bounds__(512) void k_gemm(
    const float* __restrict__ qW, const float* __restrict__ qb,
    const float* __restrict__ kW, const float* __restrict__ kb,
    const float* __restrict__ vW, const float* __restrict__ vb)
{
    int mat = blockIdx.y;
    const float* Wm = (mat == 0) ? qW : (mat == 1) ? kW : vW;
    const float* bm = (mat == 0) ? qb : (mat == 1) ? kb : vb;
    int row0 = blockIdx.x * 8;
    int t = threadIdx.x;
    int s  = t >> 7;          /* split 0..3 (warps 4s..4s+3) */
    int u  = t & 127;
    int rg = u >> 5;          /* rows rg*2, rg*2+1 (constant per warp) */
    int cg = u & 31;          /* cols cg*2, cg*2+1 */

    __shared__ __align__(16) float sA[4][GKT][10];     /* [split][k][row+pad] */
    __shared__ __align__(16) float sW[4][GKT][64];
    __shared__ __align__(16) float sAcc[4][8][65];

    float a00 = 0.f, a01 = 0.f, a10 = 0.f, a11 = 0.f;

    for (int kc = s; kc < 59; kc += 4) {
        int k0 = kc * GKT;
        /* A tile: 8 rows x 16 k (128 elems by 128 threads), transposed store */
        {
            int r = u >> 4, kk = u & 15;
            int k = k0 + kk;
            sA[s][kk][r] = (k < DED) ? g_den[(size_t)(row0 + r) * DED + k] : 0.f;
        }
        /* W tile: 16 k x 64 cols (2 x float4 per thread) */
        {
            int kk = u >> 4, c4 = u & 15;
            #pragma unroll
            for (int h = 0; h < 2; h++) {
                int kkk = kk + h*8;
                int k = k0 + kkk;
                float4 wv = (k < DED) ? *(const float4*)(Wm + (size_t)k*64 + c4*4)
                                      : make_float4(0.f,0.f,0.f,0.f);
                *(float4*)&sW[s][kkk][c4*4] = wv;
            }
        }
        asm volatile("bar.sync %0, 128;" :: "r"(s+1) : "memory");
        #pragma unroll
        for (int kk = 0; kk < GKT; kk++) {
            float2 a = *(const float2*)&sA[s][kk][rg*2];
            float2 w = *(const float2*)&sW[s][kk][cg*2];
            a00 += a.x*w.x; a01 += a.x*w.y;
            a10 += a.y*w.x; a11 += a.y*w.y;
        }
        asm volatile("bar.sync %0, 128;" :: "r"(s+1) : "memory");
    }
    sAcc[s][rg*2  ][cg*2  ] = a00; sAcc[s][rg*2  ][cg*2+1] = a01;
    sAcc[s][rg*2+1][cg*2  ] = a10; sAcc[s][rg*2+1][cg*2+1] = a11;
    __syncthreads();

    /* combine splits: 512 outputs, 1 per thread */
    int c = t >> 3, r = t & 7;
    float v = sAcc[0][r][c] + sAcc[1][r][c] + sAcc[2][r][c] + sAcc[3][r][c] + bm[c];
    if (mat == 1) g_Kt[(size_t)c * BATCH + row0 + r] = v;
    else {
        float* dst = (mat == 0) ? g_Q : g_V;
        dst[(size_t)(row0 + r) * 64 + c] = v;
    }
}

/* ================= K3: per-(band,graph) GAT + pooling ==================== */
__global__ __launch_bounds__(512) void k_gat(
    const float* __restrict__ x, const int* __restrict__ ei,
    const float* __restrict__ W, const float* __restrict__ asrc,
    const float* __restrict__ adst, const float* __restrict__ gbias)
{
    int b = blockIdx.x, band = blockIdx.y;
    int t = threadIdx.x;
    int w = t >> 5, lane = t & 31;

    __shared__ float s_xn[NPG][FIN];
    __shared__ __align__(16) float s_xt[NPG*NH*4];
    __shared__ float s_als[NPG*NH], s_ald[NPG*NH];
    __shared__ unsigned short s_tmp[NEDG];
    __shared__ unsigned char  s_srcl[NEDG];
    __shared__ int s_cntw[16][64];   /* per-warp counts -> bases -> cursors */
    __shared__ int s_cnt[64];        /* per-dst totals */
    __shared__ int s_excl[64];       /* exclusive scan */
    __shared__ float s_W[FIN*24], s_as[24], s_ad[24], s_bias[NC];
    __shared__ float s_bnp[FIN][2];
    __shared__ float s_no[NPG*4];
    __shared__ float s_pool[NC];

    /* -------- phase 0: params + init -------- */
    for (int i = t; i < 16*64; i += 512) ((int*)s_cntw)[i] = 0;
    if (t < 120)       s_W[t] = W[band*120 + t];
    else if (t < 144)  s_as[t-120] = asrc[band*24 + (t-120)];
    else if (t < 168)  s_ad[t-144] = adst[band*24 + (t-144)];
    else if (t < 171) { s_bias[t-168] = gbias[band*3 + (t-168)]; s_pool[t-168] = 0.f; }
    else if (t < 181) { int i = t-171; s_bnp[i/2][i%2] = g_bn[band][i/2][i%2]; }
    if (t >= 200 && t < 200 + NPG*4) s_no[t-200] = 0.f;
    __syncthreads();

    /* -------- phase 1: BN(x) load + edge stash + per-warp dst counts ------ */
    if (t < NPG * FIN) {
        int l = t / FIN, f = t % FIN;
        float v = x[(size_t)band * NNODES * FIN + (size_t)(b*NPG + l) * FIN + f];
        s_xn[l][f] = v * s_bnp[f][0] + s_bnp[f][1];
    }
    {
        const int* sp = ei + (size_t)band * 2 * NE + (size_t)b * EG;
        const int* dp = sp + NE;
        int base = b * NPG;
        for (int e = t; e < NEDG; e += 512) {
            int ls, ld;
            if (e < EG) { ls = sp[e] - base; ld = dp[e] - base; }
            else        { ls = ld = e - EG; }                 /* self loops */
            s_tmp[e] = (unsigned short)(ls | (ld << 8));
            atomicAdd(&s_cntw[w][ld], 1);
        }
    }
    __syncthreads();

    /* -------- phase 2a: per-warp base conversion | xt = xn @ W ----------- */
    if (t < 64) {
        int c = 0;
        #pragma unroll
        for (int ww = 0; ww < 16; ww++) {
            int tmp = s_cntw[ww][t]; s_cntw[ww][t] = c; c += tmp;
        }
        s_cnt[t] = c;
    } else {
        for (int idx = t - 64; idx < NPG * 24; idx += 448) {
            int l = idx / 24, k = idx % 24;
            float acc = s_xn[l][0]*s_W[k]    + s_xn[l][1]*s_W[24+k]
                      + s_xn[l][2]*s_W[48+k] + s_xn[l][3]*s_W[72+k]
                      + s_xn[l][4]*s_W[96+k];
            int h = k / 3, c = k % 3;
            s_xt[l*32 + h*4 + c] = acc;
        }
    }
    __syncthreads();

    /* -------- phase 2b: warp0 scan | others: attention logits ------------ */
    if (w == 0) {
        int c0 = s_cnt[lane], c1 = s_cnt[lane + 32];
        int v0 = c0, v1 = c1;
        #pragma unroll
        for (int o = 1; o < 32; o <<= 1) {
            int n0 = __shfl_up_sync(0xffffffffu, v0, o);
            int n1 = __shfl_up_sync(0xffffffffu, v1, o);
            if (lane >= o) { v0 += n0; v1 += n1; }
        }
        v1 += __shfl_sync(0xffffffffu, v0, 31);
        s_excl[lane]      = v0 - c0;
        s_excl[lane + 32] = v1 - c1;
    } else {
        for (int idx = t - 32; idx < NPG * NH; idx += 480) {
            int l = idx >> 3, h = idx & 7;
            const float* xp = &s_xt[l*32 + h*4];
            s_als[idx] = xp[0]*s_as[h*3] + xp[1]*s_as[h*3+1] + xp[2]*s_as[h*3+2];
            s_ald[idx] = xp[0]*s_ad[h*3] + xp[1]*s_ad[h*3+1] + xp[2]*s_ad[h*3+2];
        }
    }
    __syncthreads();

    /* -------- phase 3: scatter into CSR via per-warp cursors ------------- */
    for (int e = t; e < NEDG; e += 512) {
        unsigned u = s_tmp[e];
        int ld = u >> 8;
        int p = s_excl[ld] + atomicAdd(&s_cntw[w][ld], 1);
        s_srcl[p] = (unsigned char)(u & 0xFF);
    }
    __syncthreads();

    /* -------- phase 4: atomic-free gather per (dst, head) ---------------- */
    if (t < NPG * NH) {
        int d = t >> 3, h = t & 7;
        int beg = s_excl[d];
        int end = beg + s_cnt[d];
        float ald = s_ald[t];
        float den = 0.f, a0 = 0.f, a1 = 0.f, a2 = 0.f;
        for (int e = beg; e < end; e++) {
            int ls = s_srcl[e];
            float ev = s_als[ls*8 + h] + ald;
            ev = ev > 0.f ? ev : 0.2f * ev;                /* leaky 0.2 */
            float wgt = __expf(ev);                        /* no max-sub needed */
            const float4 xv = *(const float4*)&s_xt[ls*32 + h*4];
            den += wgt; a0 += wgt*xv.x; a1 += wgt*xv.y; a2 += wgt*xv.z;
        }
        float inv = 0.125f / den;                          /* /denom then head-mean */
        atomicAdd(&s_no[d*4+0], a0*inv);
        atomicAdd(&s_no[d*4+1], a1*inv);
        atomicAdd(&s_no[d*4+2], a2*inv);
    }
    __syncthreads();

    /* -------- phase 5: bias + elu + graph mean-pool ---------------------- */
    if (t < NPG * NC) {
        int d = t / 3, c = t % 3;
        float v = s_no[d*4+c] + s_bias[c];
        v = v > 0.f ? v : expm1f(v);
        atomicAdd(&s_pool[c], v);
    }
    __syncthreads();
    if (t < NC) g_xcat[b*15 + band*3 + t] = s_pool[t] * (1.f/62.f);
}

/* == K4: fg-FC + 512x512 attention + final FC + elu (4 Q rows / block) === */
__global__ __launch_bounds__(256) void k_attn(
    float* __restrict__ out, const float* __restrict__ faW,
    const float* __restrict__ fab, const float* __restrict__ fgW,
    const float* __restrict__ fgb)
{
    __shared__ float s_q[4*64], s_xo[4*64], s_sc[4*512], s_de[4*64];
    __shared__ float s_part[8][4];
    __shared__ float s_inv[4];
    int t = threadIdx.x, rowbase = blockIdx.x * 4;

    /* fold fg branch: s_xo = elu(xcat @ fgW + fgb) */
    {
        int r = t >> 6, c = t & 63;
        float acc = fgb[c];
        #pragma unroll
        for (int i = 0; i < 15; i++)
            acc += g_xcat[(rowbase+r)*15 + i] * fgW[i*64 + c];
        s_xo[t] = acc > 0.f ? acc : expm1f(acc);
        s_q[t]  = g_Q[(rowbase+r)*64 + c];
    }
    __syncthreads();

    float ps[4];
    {
        int j0 = t, j1 = t + 256;
        float acc[4][2] = {};
        #pragma unroll 8
        for (int c = 0; c < 64; c++) {
            float k0 = g_Kt[c*BATCH + j0], k1 = g_Kt[c*BATCH + j1];
            #pragma unroll
            for (int r = 0; r < 4; r++) {
                float qv = s_q[r*64 + c];
                acc[r][0] += qv * k0; acc[r][1] += qv * k1;
            }
        }
        #pragma unroll
        for (int r = 0; r < 4; r++) {
            float p0 = __expf(acc[r][0] * 0.125f);
            float p1 = __expf(acc[r][1] * 0.125f);
            s_sc[r*512 + j0] = p0; s_sc[r*512 + j1] = p1;
            ps[r] = p0 + p1;
        }
    }
    #pragma unroll
    for (int o = 16; o > 0; o >>= 1) {
        #pragma unroll
        for (int r = 0; r < 4; r++) ps[r] += __shfl_xor_sync(0xffffffffu, ps[r], o);
    }
    { int w = t >> 5, lane = t & 31;
      if (lane == 0) { s_part[w][0]=ps[0]; s_part[w][1]=ps[1]; s_part[w][2]=ps[2]; s_part[w][3]=ps[3]; } }
    __syncthreads();
    if (t < 4) {
        float s = 0.f;
        #pragma unroll
        for (int w = 0; w < 8; w++) s += s_part[w][t];
        s_inv[t] = 1.f / s;
    }
    __syncthreads();

    {
        int r = t >> 6, c = t & 63;
        const float* vp = g_V + c;
        const float* pp = &s_sc[r*512];
        float b0=0.f, b1=0.f, b2=0.f, b3=0.f;
        for (int j = 0; j < 512; j += 4) {
            b0 += pp[j]   * vp[(j)  *64];
            b1 += pp[j+1] * vp[(j+1)*64];
            b2 += pp[j+2] * vp[(j+2)*64];
            b3 += pp[j+3] * vp[(j+3)*64];
        }
        s_de[t] = ((b0+b1)+(b2+b3)) * s_inv[r];
    }
    __syncthreads();

    if (t < 12) {
        int r = t / 3, c = t % 3;
        float acc = fab[c];
        #pragma unroll 8
        for (int i = 0; i < 64; i++) {
            acc += s_xo[r*64 + i] * faW[i*3 + c];
            acc += s_de[r*64 + i] * faW[(64+i)*3 + c];
        }
        acc = acc > 0.f ? acc : expm1f(acc);
        out[(rowbase+r)*3 + c] = acc;
    }
}

/* ============================== launcher ================================ */
extern "C" void kernel_launch(void* const* d_in, const int* in_sizes, int n_in,
                              void* d_out, int out_size)
{
    const float* x     = (const float*)d_in[0];
    const int*   ei    = (const int*)  d_in[1];
    const float* de    = (const float*)d_in[3];
    const float* bng   = (const float*)d_in[4];
    const float* bnb   = (const float*)d_in[5];
    const float* W     = (const float*)d_in[6];
    const float* asrc  = (const float*)d_in[7];
    const float* adst  = (const float*)d_in[8];
    const float* gbias = (const float*)d_in[9];
    const float* fgW   = (const float*)d_in[10];
    const float* fgb   = (const float*)d_in[11];
    const float* lng   = (const float*)d_in[12];
    const float* lnb   = (const float*)d_in[13];
    const float* qW    = (const float*)d_in[14];
    const float* qb    = (const float*)d_in[15];
    const float* kW    = (const float*)d_in[16];
    const float* kb    = (const float*)d_in[17];
    const float* vW    = (const float*)d_in[18];
    const float* vb    = (const float*)d_in[19];
    const float* faW   = (const float*)d_in[20];
    const float* fab   = (const float*)d_in[21];
    float* out = (float*)d_out;

    k_pre<<<184, 256>>>(x, de, lng, lnb);
    k_bnfin<<<1, 64>>>(bng, bnb);
    k_gemm<<<dim3(64, 3), 512>>>(qW, qb, kW, kb, vW, vb);
    k_gat<<<dim3(BATCH, NB), 512>>>(x, ei, W, asrc, adst, gbias);
    k_attn<<<128, 256>>>(out, faW, fab, fgW, fgb);
}

// round 7
// speedup vs baseline: 1.7273x; 1.1886x over previous
#include <cuda_runtime.h>

#define NB    5
#define BATCH 512
#define NPG   62
#define NNODES (BATCH*NPG)      /* 31744 */
#define FIN   5
#define NH    8
#define NC    3
#define EG    992               /* edges per graph */
#define NE    (BATCH*EG)        /* 507904 edges per band */
#define NEDG  (EG+NPG)          /* 1054 incl self loops */
#define DED   930

/* ---------------- device scratch (no allocations allowed) ---------------- */
__device__ float g_stats[NB][10];                 /* zero-init; re-zeroed by k_bnfin */
__device__ float g_bn[NB][FIN][2];
__device__ __align__(16) float g_xcat[BATCH*15];
__device__ __align__(16) float g_Q[BATCH*64];
__device__ __align__(16) float g_Kt[64*BATCH];    /* transposed K */
__device__ __align__(16) float g_V[BATCH*64];
__device__ __align__(16) float g_den[BATCH*DED];  /* layernormed de */

/* ================= K1a: batchnorm statistics (partial sums) ============== */
__global__ __launch_bounds__(256) void k_stats(const float* __restrict__ x)
{
    int band = blockIdx.x, slice = blockIdx.y;
    const float* xb = x + (size_t)band * NNODES * FIN;
    float s[5] = {0,0,0,0,0}, q[5] = {0,0,0,0,0};
    for (int n = slice * 256 + threadIdx.x; n < NNODES; n += 24 * 256) {
        const float* p = xb + (size_t)n * FIN;
        #pragma unroll
        for (int f = 0; f < 5; f++) { float v = p[f]; s[f] += v; q[f] += v*v; }
    }
    #pragma unroll
    for (int o = 16; o > 0; o >>= 1) {
        #pragma unroll
        for (int f = 0; f < 5; f++) {
            s[f] += __shfl_xor_sync(0xffffffffu, s[f], o);
            q[f] += __shfl_xor_sync(0xffffffffu, q[f], o);
        }
    }
    __shared__ float red[8][10];
    int w = threadIdx.x >> 5, lane = threadIdx.x & 31;
    if (lane == 0) {
        #pragma unroll
        for (int f = 0; f < 5; f++) { red[w][f] = s[f]; red[w][5+f] = q[f]; }
    }
    __syncthreads();
    if (threadIdx.x < 10) {
        float acc = 0.f;
        #pragma unroll
        for (int i = 0; i < 8; i++) acc += red[i][threadIdx.x];
        atomicAdd(&g_stats[band][threadIdx.x], acc);
    }
}

/* ================= K1b: finalize BN scale/shift, reset stats ============= */
__global__ void k_bnfin(const float* __restrict__ gamma, const float* __restrict__ beta)
{
    int t = threadIdx.x;                       /* 64 threads */
    if (t < NB * FIN) {
        int band = t / 5, f = t % 5;
        float ss = g_stats[band][f], qq = g_stats[band][5+f];
        float mean = ss * (1.f / NNODES);
        float var  = qq * (1.f / NNODES) - mean * mean;
        float sc   = rsqrtf(var + 1e-5f) * gamma[t];
        g_bn[band][f][0] = sc;
        g_bn[band][f][1] = beta[t] - mean * sc;
    }
    __syncthreads();
    for (int i = t; i < NB * 10; i += blockDim.x)
        ((float*)g_stats)[i] = 0.f;            /* ready for next replay */
}

/* ================= K2a: LayerNorm (warp per row) ========================= */
__global__ __launch_bounds__(128) void k_ln(
    const float* __restrict__ de, const float* __restrict__ lng,
    const float* __restrict__ lnb)
{
    int w = threadIdx.x >> 5, lane = threadIdx.x & 31;
    int row = blockIdx.x * 4 + w;
    const float* dr = de + (size_t)row * DED;
    float v[30];
    float ssum = 0.f, ssq = 0.f;
    #pragma unroll
    for (int i = 0; i < 30; i++) {
        int j = lane + i*32;
        float z = (j < DED) ? dr[j] : 0.f;
        v[i] = z; ssum += z; ssq += z*z;
    }
    #pragma unroll
    for (int o = 16; o > 0; o >>= 1) {
        ssum += __shfl_xor_sync(0xffffffffu, ssum, o);
        ssq  += __shfl_xor_sync(0xffffffffu, ssq, o);
    }
    float mu   = ssum * (1.f/DED);
    float rstd = rsqrtf(ssq * (1.f/DED) - mu*mu + 1e-5f);
    float* outp = g_den + (size_t)row * DED;
    #pragma unroll
    for (int i = 0; i < 30; i++) {
        int j = lane + i*32;
        if (j < DED) outp[j] = (v[i] - mu) * rstd * lng[j] + lnb[j];
    }
}

/* ===== K2b: QKV GEMM [512,930]@[930,64], 8-row tiles, 4-way split-K ===== */
#define GKT 16
__global__ __launch_bounds__(512) void k_gemm(
    const float* __restrict__ qW, const float* __restrict__ qb,
    const float* __restrict__ kW, const float* __restrict__ kb,
    const float* __restrict__ vW, const float* __restrict__ vb)
{
    int mat = blockIdx.y;
    const float* Wm = (mat == 0) ? qW : (mat == 1) ? kW : vW;
    const float* bm = (mat == 0) ? qb : (mat == 1) ? kb : vb;
    int row0 = blockIdx.x * 8;
    int t = threadIdx.x;
    int s  = t >> 7;          /* split 0..3 */
    int u  = t & 127;
    int rg = u >> 5;
    int cg = u & 31;

    __shared__ __align__(16) float sA[4][GKT][10];
    __shared__ __align__(16) float sW[4][GKT][64];
    __shared__ __align__(16) float sAcc[4][8][65];

    float a00 = 0.f, a01 = 0.f, a10 = 0.f, a11 = 0.f;

    for (int kc = s; kc < 59; kc += 4) {
        int k0 = kc * GKT;
        {
            int r = u >> 4, kk = u & 15;
            int k = k0 + kk;
            sA[s][kk][r] = (k < DED) ? g_den[(size_t)(row0 + r) * DED + k] : 0.f;
        }
        {
            int kk = u >> 4, c4 = u & 15;
            #pragma unroll
            for (int h = 0; h < 2; h++) {
                int kkk = kk + h*8;
                int k = k0 + kkk;
                float4 wv = (k < DED) ? *(const float4*)(Wm + (size_t)k*64 + c4*4)
                                      : make_float4(0.f,0.f,0.f,0.f);
                *(float4*)&sW[s][kkk][c4*4] = wv;
            }
        }
        asm volatile("bar.sync %0, 128;" :: "r"(s+1) : "memory");
        #pragma unroll
        for (int kk = 0; kk < GKT; kk++) {
            float2 a = *(const float2*)&sA[s][kk][rg*2];
            float2 w = *(const float2*)&sW[s][kk][cg*2];
            a00 += a.x*w.x; a01 += a.x*w.y;
            a10 += a.y*w.x; a11 += a.y*w.y;
        }
        asm volatile("bar.sync %0, 128;" :: "r"(s+1) : "memory");
    }
    sAcc[s][rg*2  ][cg*2  ] = a00; sAcc[s][rg*2  ][cg*2+1] = a01;
    sAcc[s][rg*2+1][cg*2  ] = a10; sAcc[s][rg*2+1][cg*2+1] = a11;
    __syncthreads();

    int c = t >> 3, r = t & 7;
    float v = sAcc[0][r][c] + sAcc[1][r][c] + sAcc[2][r][c] + sAcc[3][r][c] + bm[c];
    if (mat == 1) g_Kt[(size_t)c * BATCH + row0 + r] = v;
    else {
        float* dst = (mat == 0) ? g_Q : g_V;
        dst[(size_t)(row0 + r) * 64 + c] = v;
    }
}

/* ================= K3: per-(band,graph) GAT + pooling ==================== */
__global__ __launch_bounds__(512) void k_gat(
    const float* __restrict__ x, const int* __restrict__ ei,
    const float* __restrict__ W, const float* __restrict__ asrc,
    const float* __restrict__ adst, const float* __restrict__ gbias)
{
    int b = blockIdx.x, band = blockIdx.y;
    int t = threadIdx.x;
    int w = t >> 5, lane = t & 31;

    __shared__ float s_xn[NPG][FIN];
    __shared__ __align__(16) float s_xt[NPG*NH*4];   /* [l][h]{x0,x1,x2,als} */
    __shared__ float s_ald[NPG*NH];
    __shared__ unsigned short s_tmp[NEDG];
    __shared__ unsigned char  s_srcl[NEDG];
    __shared__ int s_cntw[16][64];
    __shared__ int s_cnt[64];
    __shared__ int s_excl[64];
    __shared__ float s_W[FIN*24], s_as[24], s_ad[24], s_bias[NC];
    __shared__ float s_bnp[FIN][2];
    __shared__ float s_no[NPG*4];
    __shared__ float s_pool[NC];

    /* -------- phase 0: params + init -------- */
    for (int i = t; i < 16*64; i += 512) ((int*)s_cntw)[i] = 0;
    if (t < 120)       s_W[t] = W[band*120 + t];
    else if (t < 144)  s_as[t-120] = asrc[band*24 + (t-120)];
    else if (t < 168)  s_ad[t-144] = adst[band*24 + (t-144)];
    else if (t < 171) { s_bias[t-168] = gbias[band*3 + (t-168)]; s_pool[t-168] = 0.f; }
    else if (t < 181) { int i = t-171; s_bnp[i/2][i%2] = g_bn[band][i/2][i%2]; }
    if (t >= 200 && t < 200 + NPG*4) s_no[t-200] = 0.f;
    __syncthreads();

    /* -------- phase 1: BN(x) load + edge stash + per-warp dst counts ------ */
    if (t < NPG * FIN) {
        int l = t / FIN, f = t % FIN;
        float v = x[(size_t)band * NNODES * FIN + (size_t)(b*NPG + l) * FIN + f];
        s_xn[l][f] = v * s_bnp[f][0] + s_bnp[f][1];
    }
    {
        const int* sp = ei + (size_t)band * 2 * NE + (size_t)b * EG;
        const int* dp = sp + NE;
        int base = b * NPG;
        for (int e = t; e < NEDG; e += 512) {
            int ls, ld;
            if (e < EG) { ls = sp[e] - base; ld = dp[e] - base; }
            else        { ls = ld = e - EG; }                 /* self loops */
            s_tmp[e] = (unsigned short)(ls | (ld << 8));
            atomicAdd(&s_cntw[w][ld], 1);
        }
    }
    __syncthreads();

    /* -------- phase 2a: per-warp base conversion | xt = xn @ W ----------- */
    if (t < 64) {
        int c = 0;
        #pragma unroll
        for (int ww = 0; ww < 16; ww++) {
            int tmp = s_cntw[ww][t]; s_cntw[ww][t] = c; c += tmp;
        }
        s_cnt[t] = c;
    } else {
        for (int idx = t - 64; idx < NPG * 24; idx += 448) {
            int l = idx / 24, k = idx % 24;
            float acc = s_xn[l][0]*s_W[k]    + s_xn[l][1]*s_W[24+k]
                      + s_xn[l][2]*s_W[48+k] + s_xn[l][3]*s_W[72+k]
                      + s_xn[l][4]*s_W[96+k];
            int h = k / 3, c = k % 3;
            s_xt[l*32 + h*4 + c] = acc;
        }
    }
    __syncthreads();

    /* -------- phase 2b: warp0 scan | others: logits (als into pad) ------- */
    if (w == 0) {
        int c0 = s_cnt[lane], c1 = s_cnt[lane + 32];
        int v0 = c0, v1 = c1;
        #pragma unroll
        for (int o = 1; o < 32; o <<= 1) {
            int n0 = __shfl_up_sync(0xffffffffu, v0, o);
            int n1 = __shfl_up_sync(0xffffffffu, v1, o);
            if (lane >= o) { v0 += n0; v1 += n1; }
        }
        v1 += __shfl_sync(0xffffffffu, v0, 31);
        s_excl[lane]      = v0 - c0;
        s_excl[lane + 32] = v1 - c1;
    } else {
        for (int idx = t - 32; idx < NPG * NH; idx += 480) {
            int l = idx >> 3, h = idx & 7;
            const float* xp = &s_xt[l*32 + h*4];
            float x0 = xp[0], x1 = xp[1], x2 = xp[2];
            s_xt[l*32 + h*4 + 3] = x0*s_as[h*3] + x1*s_as[h*3+1] + x2*s_as[h*3+2];
            s_ald[idx]           = x0*s_ad[h*3] + x1*s_ad[h*3+1] + x2*s_ad[h*3+2];
        }
    }
    __syncthreads();

    /* -------- phase 3: scatter into CSR via per-warp cursors ------------- */
    for (int e = t; e < NEDG; e += 512) {
        unsigned u = s_tmp[e];
        int ld = u >> 8;
        int p = s_excl[ld] + atomicAdd(&s_cntw[w][ld], 1);
        s_srcl[p] = (unsigned char)(u & 0xFF);
    }
    __syncthreads();

    /* -------- phase 4: atomic-free gather per (dst, head) ---------------- */
    if (t < NPG * NH) {
        int d = t >> 3, h = t & 7;
        int beg = s_excl[d];
        int end = beg + s_cnt[d];
        float ald = s_ald[t];
        float den = 0.f, a0 = 0.f, a1 = 0.f, a2 = 0.f;
        #pragma unroll 2
        for (int e = beg; e < end; e++) {
            int ls = s_srcl[e];
            const float4 xv = *(const float4*)&s_xt[ls*32 + h*4];  /* x0,x1,x2,als */
            float ev = xv.w + ald;
            ev = fmaxf(ev, 0.2f * ev);                 /* leaky 0.2 */
            float wgt = __expf(ev);                    /* no max-sub needed */
            den += wgt; a0 += wgt*xv.x; a1 += wgt*xv.y; a2 += wgt*xv.z;
        }
        float inv = 0.125f / den;                      /* /denom then head-mean */
        atomicAdd(&s_no[d*4+0], a0*inv);
        atomicAdd(&s_no[d*4+1], a1*inv);
        atomicAdd(&s_no[d*4+2], a2*inv);
    }
    __syncthreads();

    /* -------- phase 5: bias + elu + graph mean-pool ---------------------- */
    if (t < NPG * NC) {
        int d = t / 3, c = t % 3;
        float v = s_no[d*4+c] + s_bias[c];
        v = v > 0.f ? v : expm1f(v);
        atomicAdd(&s_pool[c], v);
    }
    __syncthreads();
    if (t < NC) g_xcat[b*15 + band*3 + t] = s_pool[t] * (1.f/62.f);
}

/* == K4: fg-FC + 512x512 attention + final FC + elu (4 rows, 512 thr) ==== */
__global__ __launch_bounds__(512) void k_attn(
    float* __restrict__ out, const float* __restrict__ faW,
    const float* __restrict__ fab, const float* __restrict__ fgW,
    const float* __restrict__ fgb)
{
    __shared__ float s_q[4*64], s_xo[4*64], s_sc[4*512], s_de[4*64];
    __shared__ float s_half[512];
    __shared__ float s_part[16][4];
    __shared__ float s_inv[4];
    int t = threadIdx.x, rowbase = blockIdx.x * 4;

    /* fold fg branch: s_xo = elu(xcat @ fgW + fgb); load Q */
    if (t < 256) {
        int r = t >> 6, c = t & 63;
        float acc = fgb[c];
        #pragma unroll
        for (int i = 0; i < 15; i++)
            acc += g_xcat[(rowbase+r)*15 + i] * fgW[i*64 + c];
        s_xo[t] = acc > 0.f ? acc : expm1f(acc);
        s_q[t]  = g_Q[(rowbase+r)*64 + c];
    }
    __syncthreads();

    /* scores: one column j per thread, 4 rows */
    float ps[4];
    {
        int j = t;
        float acc[4] = {0.f, 0.f, 0.f, 0.f};
        #pragma unroll 8
        for (int c = 0; c < 64; c++) {
            float kv = g_Kt[c*BATCH + j];
            #pragma unroll
            for (int r = 0; r < 4; r++) acc[r] += s_q[r*64 + c] * kv;
        }
        #pragma unroll
        for (int r = 0; r < 4; r++) {
            float p = __expf(acc[r] * 0.125f);
            s_sc[r*512 + j] = p;
            ps[r] = p;
        }
    }
    #pragma unroll
    for (int o = 16; o > 0; o >>= 1) {
        #pragma unroll
        for (int r = 0; r < 4; r++) ps[r] += __shfl_xor_sync(0xffffffffu, ps[r], o);
    }
    { int w = t >> 5, lane = t & 31;
      if (lane == 0) { s_part[w][0]=ps[0]; s_part[w][1]=ps[1]; s_part[w][2]=ps[2]; s_part[w][3]=ps[3]; } }
    __syncthreads();
    if (t < 4) {
        float s = 0.f;
        #pragma unroll
        for (int w = 0; w < 16; w++) s += s_part[w][t];
        s_inv[t] = 1.f / s;
    }
    __syncthreads();

    /* x_de = (P @ V): each thread covers half the j-range of one (r,c) */
    {
        int r = t >> 7, half = (t >> 6) & 1, c = t & 63;
        const float* vp = g_V + c + half*256*64;
        const float* pp = &s_sc[r*512 + half*256];
        float b0=0.f, b1=0.f, b2=0.f, b3=0.f;
        for (int j = 0; j < 256; j += 4) {
            b0 += pp[j]   * vp[(j)  *64];
            b1 += pp[j+1] * vp[(j+1)*64];
            b2 += pp[j+2] * vp[(j+2)*64];
            b3 += pp[j+3] * vp[(j+3)*64];
        }
        s_half[t] = (b0+b1)+(b2+b3);
    }
    __syncthreads();
    if (t < 256) {
        int r = t >> 6, c = t & 63;
        s_de[t] = (s_half[r*128 + c] + s_half[r*128 + 64 + c]) * s_inv[r];
    }
    __syncthreads();

    if (t < 12) {
        int r = t / 3, c = t % 3;
        float acc = fab[c];
        #pragma unroll 8
        for (int i = 0; i < 64; i++) {
            acc += s_xo[r*64 + i] * faW[i*3 + c];
            acc += s_de[r*64 + i] * faW[(64+i)*3 + c];
        }
        acc = acc > 0.f ? acc : expm1f(acc);
        out[(rowbase+r)*3 + c] = acc;
    }
}

/* ============================== launcher ================================ */
extern "C" void kernel_launch(void* const* d_in, const int* in_sizes, int n_in,
                              void* d_out, int out_size)
{
    const float* x     = (const float*)d_in[0];
    const int*   ei    = (const int*)  d_in[1];
    const float* de    = (const float*)d_in[3];
    const float* bng   = (const float*)d_in[4];
    const float* bnb   = (const float*)d_in[5];
    const float* W     = (const float*)d_in[6];
    const float* asrc  = (const float*)d_in[7];
    const float* adst  = (const float*)d_in[8];
    const float* gbias = (const float*)d_in[9];
    const float* fgW   = (const float*)d_in[10];
    const float* fgb   = (const float*)d_in[11];
    const float* lng   = (const float*)d_in[12];
    const float* lnb   = (const float*)d_in[13];
    const float* qW    = (const float*)d_in[14];
    const float* qb    = (const float*)d_in[15];
    const float* kW    = (const float*)d_in[16];
    const float* kb    = (const float*)d_in[17];
    const float* vW    = (const float*)d_in[18];
    const float* vb    = (const float*)d_in[19];
    const float* faW   = (const float*)d_in[20];
    const float* fab   = (const float*)d_in[21];
    float* out = (float*)d_out;

    /* strictly sequential, default stream — capture-safe */
    k_ln<<<128, 128>>>(de, lng, lnb);
    k_stats<<<dim3(NB, 24), 256>>>(x);
    k_bnfin<<<1, 64>>>(bng, bnb);
    k_gemm<<<dim3(64, 3), 512>>>(qW, qb, kW, kb, vW, vb);
    k_gat<<<dim3(BATCH, NB), 512>>>(x, ei, W, asrc, adst, gbias);
    k_attn<<<128, 512>>>(out, faW, fab, fgW, fgb);
}

// round 8
// speedup vs baseline: 1.8531x; 1.0728x over previous
#include <cuda_runtime.h>

#define NB    5
#define BATCH 512
#define NPG   62
#define NNODES (BATCH*NPG)      /* 31744 */
#define FIN   5
#define NH    8
#define NC    3
#define EG    992               /* edges per graph */
#define NE    (BATCH*EG)        /* 507904 edges per band */
#define NEDG  (EG+NPG)          /* 1054 incl self loops */
#define DED   930
#define KCH   117               /* ceil(930/8) k-chunks of 8 */

/* ---------------- device scratch (no allocations allowed) ---------------- */
__device__ float g_stats[NB][10];                 /* zero-init; re-zeroed by k_bnfin */
__device__ float g_bn[NB][FIN][2];
__device__ __align__(16) float g_xcat[BATCH*15];
__device__ __align__(16) float g_Q[BATCH*64];
__device__ __align__(16) float g_Kt[64*BATCH];    /* transposed K */
__device__ __align__(16) float g_V[BATCH*64];

/* ====== K1: fused QKV-GEMM (blocks 0..191, inline LN) + BN stats ========= */
struct GemmSmem {
    float sN[8][948];                              /* normalized A rows, padded */
    union {
        float sW[8][8][64];                        /* [split][kk][col]   */
        float sAcc[8][8][68];                      /* [split][row][col]  */
    } u;
};

__global__ __launch_bounds__(512) void k_fused(
    const float* __restrict__ de,  const float* __restrict__ lng,
    const float* __restrict__ lnb,
    const float* __restrict__ qW,  const float* __restrict__ qb,
    const float* __restrict__ kW,  const float* __restrict__ kb,
    const float* __restrict__ vW,  const float* __restrict__ vb,
    const float* __restrict__ x)
{
    __shared__ union { GemmSmem g; float red[16][10]; } S;
    int bid = blockIdx.x;
    int t = threadIdx.x, w = t >> 5, lane = t & 31;

    if (bid < 192) {
        /* ---------------- QKV GEMM with inline LayerNorm ---------------- */
        int mat = bid / 64, tile = bid % 64;
        int row0 = tile * 8;
        const float* Wm = (mat == 0) ? qW : (mat == 1) ? kW : vW;
        const float* bm = (mat == 0) ? qb : (mat == 1) ? kb : vb;

        /* LN: warp per row (warps 0..7) */
        if (w < 8) {
            const float* dr = de + (size_t)(row0 + w) * DED;
            float v[30];
            float ssum = 0.f, ssq = 0.f;
            #pragma unroll
            for (int i = 0; i < 30; i++) {
                int j = lane + i*32;
                float z = (j < DED) ? dr[j] : 0.f;
                v[i] = z; ssum += z; ssq += z*z;
            }
            #pragma unroll
            for (int o = 16; o > 0; o >>= 1) {
                ssum += __shfl_xor_sync(0xffffffffu, ssum, o);
                ssq  += __shfl_xor_sync(0xffffffffu, ssq, o);
            }
            float mu   = ssum * (1.f/DED);
            float rstd = rsqrtf(ssq * (1.f/DED) - mu*mu + 1e-5f);
            #pragma unroll
            for (int i = 0; i < 30; i++) {
                int j = lane + i*32;
                if (j < DED) S.g.sN[w][j] = (v[i] - mu) * rstd * lng[j] + lnb[j];
            }
            for (int j = DED + lane; j < 948; j += 32) S.g.sN[w][j] = 0.f;
        }
        __syncthreads();

        int s  = t >> 6;          /* split 0..7 (64-thread group)   */
        int u  = t & 63;
        int rg = u >> 4;          /* rows rg*2, rg*2+1              */
        int cg = u & 15;          /* cols cg*4 .. +3                */

        float a0c0=0.f,a0c1=0.f,a0c2=0.f,a0c3=0.f;
        float a1c0=0.f,a1c1=0.f,a1c2=0.f,a1c3=0.f;

        for (int kc = s; kc < KCH; kc += 8) {
            int k0 = kc * 8;
            /* stage W chunk: 8 k x 64 cols, 2 float4 per thread */
            #pragma unroll
            for (int j = 0; j < 2; j++) {
                int kk = rg + 4*j;
                int k = k0 + kk;
                float4 wv = (k < DED) ? *(const float4*)(Wm + (size_t)k*64 + cg*4)
                                      : make_float4(0.f,0.f,0.f,0.f);
                *(float4*)&S.g.u.sW[s][kk][cg*4] = wv;
            }
            asm volatile("bar.sync %0, 64;" :: "r"(s+1) : "memory");
            #pragma unroll
            for (int kk = 0; kk < 8; kk++) {
                float a0 = S.g.sN[rg*2  ][k0+kk];
                float a1 = S.g.sN[rg*2+1][k0+kk];
                float4 wv = *(const float4*)&S.g.u.sW[s][kk][cg*4];
                a0c0 += a0*wv.x; a0c1 += a0*wv.y; a0c2 += a0*wv.z; a0c3 += a0*wv.w;
                a1c0 += a1*wv.x; a1c1 += a1*wv.y; a1c2 += a1*wv.z; a1c3 += a1*wv.w;
            }
            asm volatile("bar.sync %0, 64;" :: "r"(s+1) : "memory");
        }
        __syncthreads();                 /* sW region reused as sAcc */
        *(float4*)&S.g.u.sAcc[s][rg*2  ][cg*4] = make_float4(a0c0,a0c1,a0c2,a0c3);
        *(float4*)&S.g.u.sAcc[s][rg*2+1][cg*4] = make_float4(a1c0,a1c1,a1c2,a1c3);
        __syncthreads();

        /* combine 8 splits: 512 outputs, one per thread */
        int r = t >> 6, c = t & 63;
        float v = bm[c];
        #pragma unroll
        for (int ss = 0; ss < 8; ss++) v += S.g.u.sAcc[ss][r][c];
        if (mat == 1) g_Kt[(size_t)c * BATCH + row0 + r] = v;
        else {
            float* dst = (mat == 0) ? g_Q : g_V;
            dst[(size_t)(row0 + r) * 64 + c] = v;
        }
    } else {
        /* ---------------- BN statistics (120 blocks) -------------------- */
        int idx = bid - 192;
        int band = idx / 24, slice = idx % 24;
        const float* xb = x + (size_t)band * NNODES * FIN;
        float sm[5] = {0,0,0,0,0}, q[5] = {0,0,0,0,0};
        for (int n = slice * 512 + t; n < NNODES; n += 24 * 512) {
            const float* p = xb + (size_t)n * FIN;
            #pragma unroll
            for (int f = 0; f < 5; f++) { float v = p[f]; sm[f] += v; q[f] += v*v; }
        }
        #pragma unroll
        for (int o = 16; o > 0; o >>= 1) {
            #pragma unroll
            for (int f = 0; f < 5; f++) {
                sm[f] += __shfl_xor_sync(0xffffffffu, sm[f], o);
                q[f]  += __shfl_xor_sync(0xffffffffu, q[f],  o);
            }
        }
        if (lane == 0) {
            #pragma unroll
            for (int f = 0; f < 5; f++) { S.red[w][f] = sm[f]; S.red[w][5+f] = q[f]; }
        }
        __syncthreads();
        if (t < 10) {
            float acc = 0.f;
            #pragma unroll
            for (int i = 0; i < 16; i++) acc += S.red[i][t];
            atomicAdd(&g_stats[band][t], acc);
        }
    }
}

/* ================= K1b: finalize BN scale/shift, reset stats ============= */
__global__ void k_bnfin(const float* __restrict__ gamma, const float* __restrict__ beta)
{
    int t = threadIdx.x;                       /* 64 threads */
    if (t < NB * FIN) {
        int band = t / 5, f = t % 5;
        float ss = g_stats[band][f], qq = g_stats[band][5+f];
        float mean = ss * (1.f / NNODES);
        float var  = qq * (1.f / NNODES) - mean * mean;
        float sc   = rsqrtf(var + 1e-5f) * gamma[t];
        g_bn[band][f][0] = sc;
        g_bn[band][f][1] = beta[t] - mean * sc;
    }
    __syncthreads();
    for (int i = t; i < NB * 10; i += blockDim.x)
        ((float*)g_stats)[i] = 0.f;            /* ready for next replay */
}

/* ================= K2: per-(band,graph) GAT + pooling ==================== */
__global__ __launch_bounds__(512) void k_gat(
    const float* __restrict__ x, const int* __restrict__ ei,
    const float* __restrict__ W, const float* __restrict__ asrc,
    const float* __restrict__ adst, const float* __restrict__ gbias)
{
    int b = blockIdx.x, band = blockIdx.y;
    int t = threadIdx.x;
    int w = t >> 5, lane = t & 31;

    __shared__ float s_xn[NPG][FIN];
    __shared__ __align__(16) float s_xt[NPG*NH*4];   /* [l][h]{x0,x1,x2,als} */
    __shared__ float s_ald[NPG*NH];
    __shared__ unsigned short s_tmp[NEDG];
    __shared__ unsigned char  s_srcl[NEDG];
    __shared__ int s_cntw[16][64];
    __shared__ int s_cnt[64];
    __shared__ int s_excl[64];
    __shared__ float s_W[FIN*24], s_as[24], s_ad[24], s_bias[NC];
    __shared__ float s_bnp[FIN][2];
    __shared__ float s_no[NPG*4];
    __shared__ float s_pool[NC];

    /* -------- phase 0: params + init -------- */
    for (int i = t; i < 16*64; i += 512) ((int*)s_cntw)[i] = 0;
    if (t < 120)       s_W[t] = W[band*120 + t];
    else if (t < 144)  s_as[t-120] = asrc[band*24 + (t-120)];
    else if (t < 168)  s_ad[t-144] = adst[band*24 + (t-144)];
    else if (t < 171) { s_bias[t-168] = gbias[band*3 + (t-168)]; s_pool[t-168] = 0.f; }
    else if (t < 181) { int i = t-171; s_bnp[i/2][i%2] = g_bn[band][i/2][i%2]; }
    if (t >= 200 && t < 200 + NPG*4) s_no[t-200] = 0.f;
    __syncthreads();

    /* -------- phase 1: BN(x) load + edge stash + per-warp dst counts ------ */
    if (t < NPG * FIN) {
        int l = t / FIN, f = t % FIN;
        float v = x[(size_t)band * NNODES * FIN + (size_t)(b*NPG + l) * FIN + f];
        s_xn[l][f] = v * s_bnp[f][0] + s_bnp[f][1];
    }
    {
        const int* sp = ei + (size_t)band * 2 * NE + (size_t)b * EG;
        const int* dp = sp + NE;
        int base = b * NPG;
        for (int e = t; e < NEDG; e += 512) {
            int ls, ld;
            if (e < EG) { ls = sp[e] - base; ld = dp[e] - base; }
            else        { ls = ld = e - EG; }                 /* self loops */
            s_tmp[e] = (unsigned short)(ls | (ld << 8));
            atomicAdd(&s_cntw[w][ld], 1);
        }
    }
    __syncthreads();

    /* -------- phase 2a: per-warp base conversion | xt = xn @ W ----------- */
    if (t < 64) {
        int c = 0;
        #pragma unroll
        for (int ww = 0; ww < 16; ww++) {
            int tmp = s_cntw[ww][t]; s_cntw[ww][t] = c; c += tmp;
        }
        s_cnt[t] = c;
    } else {
        for (int idx = t - 64; idx < NPG * 24; idx += 448) {
            int l = idx / 24, k = idx % 24;
            float acc = s_xn[l][0]*s_W[k]    + s_xn[l][1]*s_W[24+k]
                      + s_xn[l][2]*s_W[48+k] + s_xn[l][3]*s_W[72+k]
                      + s_xn[l][4]*s_W[96+k];
            int h = k / 3, c = k % 3;
            s_xt[l*32 + h*4 + c] = acc;
        }
    }
    __syncthreads();

    /* -------- phase 2b: warp0 scan | others: logits (als into pad) ------- */
    if (w == 0) {
        int c0 = s_cnt[lane], c1 = s_cnt[lane + 32];
        int v0 = c0, v1 = c1;
        #pragma unroll
        for (int o = 1; o < 32; o <<= 1) {
            int n0 = __shfl_up_sync(0xffffffffu, v0, o);
            int n1 = __shfl_up_sync(0xffffffffu, v1, o);
            if (lane >= o) { v0 += n0; v1 += n1; }
        }
        v1 += __shfl_sync(0xffffffffu, v0, 31);
        s_excl[lane]      = v0 - c0;
        s_excl[lane + 32] = v1 - c1;
    } else {
        for (int idx = t - 32; idx < NPG * NH; idx += 480) {
            int l = idx >> 3, h = idx & 7;
            const float* xp = &s_xt[l*32 + h*4];
            float x0 = xp[0], x1 = xp[1], x2 = xp[2];
            s_xt[l*32 + h*4 + 3] = x0*s_as[h*3] + x1*s_as[h*3+1] + x2*s_as[h*3+2];
            s_ald[idx]           = x0*s_ad[h*3] + x1*s_ad[h*3+1] + x2*s_ad[h*3+2];
        }
    }
    __syncthreads();

    /* -------- phase 3: scatter into CSR via per-warp cursors ------------- */
    for (int e = t; e < NEDG; e += 512) {
        unsigned u = s_tmp[e];
        int ld = u >> 8;
        int p = s_excl[ld] + atomicAdd(&s_cntw[w][ld], 1);
        s_srcl[p] = (unsigned char)(u & 0xFF);
    }
    __syncthreads();

    /* -------- phase 4: atomic-free gather per (dst, head) ---------------- */
    if (t < NPG * NH) {
        int d = t >> 3, h = t & 7;
        int beg = s_excl[d];
        int end = beg + s_cnt[d];
        float ald = s_ald[t];
        float den = 0.f, a0 = 0.f, a1 = 0.f, a2 = 0.f;
        #pragma unroll 2
        for (int e = beg; e < end; e++) {
            int ls = s_srcl[e];
            const float4 xv = *(const float4*)&s_xt[ls*32 + h*4];  /* x0,x1,x2,als */
            float ev = xv.w + ald;
            ev = fmaxf(ev, 0.2f * ev);                 /* leaky 0.2 */
            float wgt = __expf(ev);                    /* no max-sub needed */
            den += wgt; a0 += wgt*xv.x; a1 += wgt*xv.y; a2 += wgt*xv.z;
        }
        float inv = 0.125f / den;                      /* /denom then head-mean */
        atomicAdd(&s_no[d*4+0], a0*inv);
        atomicAdd(&s_no[d*4+1], a1*inv);
        atomicAdd(&s_no[d*4+2], a2*inv);
    }
    __syncthreads();

    /* -------- phase 5: bias + elu + graph mean-pool ---------------------- */
    if (t < NPG * NC) {
        int d = t / 3, c = t % 3;
        float v = s_no[d*4+c] + s_bias[c];
        v = v > 0.f ? v : expm1f(v);
        atomicAdd(&s_pool[c], v);
    }
    __syncthreads();
    if (t < NC) g_xcat[b*15 + band*3 + t] = s_pool[t] * (1.f/62.f);
}

/* == K3: fg-FC + 512x512 attention + final FC + elu (4 rows, 512 thr) ==== */
__global__ __launch_bounds__(512) void k_attn(
    float* __restrict__ out, const float* __restrict__ faW,
    const float* __restrict__ fab, const float* __restrict__ fgW,
    const float* __restrict__ fgb)
{
    __shared__ float s_q[4*64], s_xo[4*64], s_sc[4*512], s_de[4*64];
    __shared__ float s_half[512];
    __shared__ float s_part[16][4];
    __shared__ float s_inv[4];
    int t = threadIdx.x, rowbase = blockIdx.x * 4;

    /* fold fg branch: s_xo = elu(xcat @ fgW + fgb); load Q */
    if (t < 256) {
        int r = t >> 6, c = t & 63;
        float acc = fgb[c];
        #pragma unroll
        for (int i = 0; i < 15; i++)
            acc += g_xcat[(rowbase+r)*15 + i] * fgW[i*64 + c];
        s_xo[t] = acc > 0.f ? acc : expm1f(acc);
        s_q[t]  = g_Q[(rowbase+r)*64 + c];
    }
    __syncthreads();

    /* scores: one column j per thread, 4 rows */
    float ps[4];
    {
        int j = t;
        float acc[4] = {0.f, 0.f, 0.f, 0.f};
        #pragma unroll 8
        for (int c = 0; c < 64; c++) {
            float kv = g_Kt[c*BATCH + j];
            #pragma unroll
            for (int r = 0; r < 4; r++) acc[r] += s_q[r*64 + c] * kv;
        }
        #pragma unroll
        for (int r = 0; r < 4; r++) {
            float p = __expf(acc[r] * 0.125f);
            s_sc[r*512 + j] = p;
            ps[r] = p;
        }
    }
    #pragma unroll
    for (int o = 16; o > 0; o >>= 1) {
        #pragma unroll
        for (int r = 0; r < 4; r++) ps[r] += __shfl_xor_sync(0xffffffffu, ps[r], o);
    }
    { int w = t >> 5, lane = t & 31;
      if (lane == 0) { s_part[w][0]=ps[0]; s_part[w][1]=ps[1]; s_part[w][2]=ps[2]; s_part[w][3]=ps[3]; } }
    __syncthreads();
    if (t < 4) {
        float s = 0.f;
        #pragma unroll
        for (int w = 0; w < 16; w++) s += s_part[w][t];
        s_inv[t] = 1.f / s;
    }
    __syncthreads();

    /* x_de = (P @ V): each thread covers half the j-range of one (r,c) */
    {
        int r = t >> 7, half = (t >> 6) & 1, c = t & 63;
        const float* vp = g_V + c + half*256*64;
        const float* pp = &s_sc[r*512 + half*256];
        float b0=0.f, b1=0.f, b2=0.f, b3=0.f;
        for (int j = 0; j < 256; j += 4) {
            b0 += pp[j]   * vp[(j)  *64];
            b1 += pp[j+1] * vp[(j+1)*64];
            b2 += pp[j+2] * vp[(j+2)*64];
            b3 += pp[j+3] * vp[(j+3)*64];
        }
        s_half[t] = (b0+b1)+(b2+b3);
    }
    __syncthreads();
    if (t < 256) {
        int r = t >> 6, c = t & 63;
        s_de[t] = (s_half[r*128 + c] + s_half[r*128 + 64 + c]) * s_inv[r];
    }
    __syncthreads();

    if (t < 12) {
        int r = t / 3, c = t % 3;
        float acc = fab[c];
        #pragma unroll 8
        for (int i = 0; i < 64; i++) {
            acc += s_xo[r*64 + i] * faW[i*3 + c];
            acc += s_de[r*64 + i] * faW[(64+i)*3 + c];
        }
        acc = acc > 0.f ? acc : expm1f(acc);
        out[(rowbase+r)*3 + c] = acc;
    }
}

/* ============================== launcher ================================ */
extern "C" void kernel_launch(void* const* d_in, const int* in_sizes, int n_in,
                              void* d_out, int out_size)
{
    const float* x     = (const float*)d_in[0];
    const int*   ei    = (const int*)  d_in[1];
    const float* de    = (const float*)d_in[3];
    const float* bng   = (const float*)d_in[4];
    const float* bnb   = (const float*)d_in[5];
    const float* W     = (const float*)d_in[6];
    const float* asrc  = (const float*)d_in[7];
    const float* adst  = (const float*)d_in[8];
    const float* gbias = (const float*)d_in[9];
    const float* fgW   = (const float*)d_in[10];
    const float* fgb   = (const float*)d_in[11];
    const float* lng   = (const float*)d_in[12];
    const float* lnb   = (const float*)d_in[13];
    const float* qW    = (const float*)d_in[14];
    const float* qb    = (const float*)d_in[15];
    const float* kW    = (const float*)d_in[16];
    const float* kb    = (const float*)d_in[17];
    const float* vW    = (const float*)d_in[18];
    const float* vb    = (const float*)d_in[19];
    const float* faW   = (const float*)d_in[20];
    const float* fab   = (const float*)d_in[21];
    float* out = (float*)d_out;

    /* strictly sequential, default stream — capture-safe */
    k_fused<<<312, 512>>>(de, lng, lnb, qW, qb, kW, kb, vW, vb, x);
    k_bnfin<<<1, 64>>>(bng, bnb);
    k_gat<<<dim3(BATCH, NB), 512>>>(x, ei, W, asrc, adst, gbias);
    k_attn<<<128, 512>>>(out, faW, fab, fgW, fgb);
}

// round 9
// speedup vs baseline: 1.9961x; 1.0772x over previous
#include <cuda_runtime.h>

#define NB    5
#define BATCH 512
#define NPG   62
#define NNODES (BATCH*NPG)      /* 31744 */
#define FIN   5
#define NH    8
#define NC    3
#define EG    992               /* edges per graph */
#define NE    (BATCH*EG)        /* 507904 edges per band */
#define NEDG  (EG+NPG)          /* 1054 incl self loops */
#define DED   930
#define KCH   117               /* ceil(930/8) k-chunks of 8 */

/* ---------------- device scratch (no allocations allowed) ---------------- */
__device__ float g_stats[NB][10];                 /* zero-init; re-zeroed by k_attn */
__device__ __align__(16) float g_xcat[BATCH*15];
__device__ __align__(16) float g_Q[BATCH*64];
__device__ __align__(16) float g_Kt[64*BATCH];    /* transposed K */
__device__ __align__(16) float g_V[BATCH*64];

/* ====== K1: fused QKV-GEMM (blocks 0..191, inline LN) + BN stats ========= */
struct GemmSmem {
    float sN[8][948];                              /* normalized A rows, padded */
    union {
        float sW[8][8][64];                        /* [split][kk][col]   */
        float sAcc[8][8][68];                      /* [split][row][col]  */
    } u;
};

__global__ __launch_bounds__(512) void k_fused(
    const float* __restrict__ de,  const float* __restrict__ lng,
    const float* __restrict__ lnb,
    const float* __restrict__ qW,  const float* __restrict__ qb,
    const float* __restrict__ kW,  const float* __restrict__ kb,
    const float* __restrict__ vW,  const float* __restrict__ vb,
    const float* __restrict__ x)
{
    __shared__ union { GemmSmem g; float red[16][10]; } S;
    int bid = blockIdx.x;
    int t = threadIdx.x, w = t >> 5, lane = t & 31;

    if (bid < 192) {
        /* ---------------- QKV GEMM with inline LayerNorm ---------------- */
        int mat = bid / 64, tile = bid % 64;
        int row0 = tile * 8;
        const float* Wm = (mat == 0) ? qW : (mat == 1) ? kW : vW;
        const float* bm = (mat == 0) ? qb : (mat == 1) ? kb : vb;

        /* LN: warp per row (warps 0..7) */
        if (w < 8) {
            const float* dr = de + (size_t)(row0 + w) * DED;
            float v[30];
            float ssum = 0.f, ssq = 0.f;
            #pragma unroll
            for (int i = 0; i < 30; i++) {
                int j = lane + i*32;
                float z = (j < DED) ? dr[j] : 0.f;
                v[i] = z; ssum += z; ssq += z*z;
            }
            #pragma unroll
            for (int o = 16; o > 0; o >>= 1) {
                ssum += __shfl_xor_sync(0xffffffffu, ssum, o);
                ssq  += __shfl_xor_sync(0xffffffffu, ssq, o);
            }
            float mu   = ssum * (1.f/DED);
            float rstd = rsqrtf(ssq * (1.f/DED) - mu*mu + 1e-5f);
            #pragma unroll
            for (int i = 0; i < 30; i++) {
                int j = lane + i*32;
                if (j < DED) S.g.sN[w][j] = (v[i] - mu) * rstd * lng[j] + lnb[j];
            }
            for (int j = DED + lane; j < 948; j += 32) S.g.sN[w][j] = 0.f;
        }
        __syncthreads();

        int s  = t >> 6;          /* split 0..7 (64-thread group)   */
        int u  = t & 63;
        int rg = u >> 4;          /* rows rg*2, rg*2+1              */
        int cg = u & 15;          /* cols cg*4 .. +3                */

        float a0c0=0.f,a0c1=0.f,a0c2=0.f,a0c3=0.f;
        float a1c0=0.f,a1c1=0.f,a1c2=0.f,a1c3=0.f;

        for (int kc = s; kc < KCH; kc += 8) {
            int k0 = kc * 8;
            #pragma unroll
            for (int j = 0; j < 2; j++) {
                int kk = rg + 4*j;
                int k = k0 + kk;
                float4 wv = (k < DED) ? *(const float4*)(Wm + (size_t)k*64 + cg*4)
                                      : make_float4(0.f,0.f,0.f,0.f);
                *(float4*)&S.g.u.sW[s][kk][cg*4] = wv;
            }
            asm volatile("bar.sync %0, 64;" :: "r"(s+1) : "memory");
            #pragma unroll
            for (int kk = 0; kk < 8; kk++) {
                float a0 = S.g.sN[rg*2  ][k0+kk];
                float a1 = S.g.sN[rg*2+1][k0+kk];
                float4 wv = *(const float4*)&S.g.u.sW[s][kk][cg*4];
                a0c0 += a0*wv.x; a0c1 += a0*wv.y; a0c2 += a0*wv.z; a0c3 += a0*wv.w;
                a1c0 += a1*wv.x; a1c1 += a1*wv.y; a1c2 += a1*wv.z; a1c3 += a1*wv.w;
            }
            asm volatile("bar.sync %0, 64;" :: "r"(s+1) : "memory");
        }
        __syncthreads();                 /* sW region reused as sAcc */
        *(float4*)&S.g.u.sAcc[s][rg*2  ][cg*4] = make_float4(a0c0,a0c1,a0c2,a0c3);
        *(float4*)&S.g.u.sAcc[s][rg*2+1][cg*4] = make_float4(a1c0,a1c1,a1c2,a1c3);
        __syncthreads();

        int r = t >> 6, c = t & 63;
        float v = bm[c];
        #pragma unroll
        for (int ss = 0; ss < 8; ss++) v += S.g.u.sAcc[ss][r][c];
        if (mat == 1) g_Kt[(size_t)c * BATCH + row0 + r] = v;
        else {
            float* dst = (mat == 0) ? g_Q : g_V;
            dst[(size_t)(row0 + r) * 64 + c] = v;
        }
    } else {
        /* ---------------- BN statistics (120 blocks) -------------------- */
        int idx = bid - 192;
        int band = idx / 24, slice = idx % 24;
        const float* xb = x + (size_t)band * NNODES * FIN;
        float sm[5] = {0,0,0,0,0}, q[5] = {0,0,0,0,0};
        for (int n = slice * 512 + t; n < NNODES; n += 24 * 512) {
            const float* p = xb + (size_t)n * FIN;
            #pragma unroll
            for (int f = 0; f < 5; f++) { float v = p[f]; sm[f] += v; q[f] += v*v; }
        }
        #pragma unroll
        for (int o = 16; o > 0; o >>= 1) {
            #pragma unroll
            for (int f = 0; f < 5; f++) {
                sm[f] += __shfl_xor_sync(0xffffffffu, sm[f], o);
                q[f]  += __shfl_xor_sync(0xffffffffu, q[f],  o);
            }
        }
        if (lane == 0) {
            #pragma unroll
            for (int f = 0; f < 5; f++) { S.red[w][f] = sm[f]; S.red[w][5+f] = q[f]; }
        }
        __syncthreads();
        if (t < 10) {
            float acc = 0.f;
            #pragma unroll
            for (int i = 0; i < 16; i++) acc += S.red[i][t];
            atomicAdd(&g_stats[band][t], acc);
        }
    }
}

/* ================= K2: per-(band,graph) GAT + pooling ==================== */
__global__ __launch_bounds__(512) void k_gat(
    const float* __restrict__ x, const int* __restrict__ ei,
    const float* __restrict__ W, const float* __restrict__ asrc,
    const float* __restrict__ adst, const float* __restrict__ gbias,
    const float* __restrict__ bng, const float* __restrict__ bnb)
{
    int b = blockIdx.x, band = blockIdx.y;
    int t = threadIdx.x;
    int w = t >> 5, lane = t & 31;

    __shared__ float s_xn[NPG][FIN];
    __shared__ __align__(16) float s_xt[NPG*NH*4];   /* [l][h]{x0,x1,x2,als} */
    __shared__ float s_ald[NPG*NH];
    __shared__ unsigned short s_tmp[NEDG];
    __shared__ unsigned char  s_srcl[NEDG];
    __shared__ int s_cntw[16][64];
    __shared__ int s_cnt[64];
    __shared__ int s_excl[64];
    __shared__ float s_W[FIN*24], s_as[24], s_ad[24], s_bias[NC];
    __shared__ float s_bnp[FIN][2];
    __shared__ float s_no[NPG*4];
    __shared__ float s_pool[NC];

    /* -------- phase 0: params + init (BN params from raw stats) -------- */
    for (int i = t; i < 16*64; i += 512) ((int*)s_cntw)[i] = 0;
    if (t < 120)       s_W[t] = W[band*120 + t];
    else if (t < 144)  s_as[t-120] = asrc[band*24 + (t-120)];
    else if (t < 168)  s_ad[t-144] = adst[band*24 + (t-168+24)];  /* == t-144 */
    else if (t < 171) { s_bias[t-168] = gbias[band*3 + (t-168)]; s_pool[t-168] = 0.f; }
    else if (t < 176) {
        int f = t - 171;
        float mean = g_stats[band][f] * (1.f/NNODES);
        float var  = g_stats[band][5+f] * (1.f/NNODES) - mean*mean;
        float sc   = rsqrtf(var + 1e-5f) * bng[band*5+f];
        s_bnp[f][0] = sc;
        s_bnp[f][1] = bnb[band*5+f] - mean*sc;
    }
    if (t >= 200 && t < 200 + NPG*4) s_no[t-200] = 0.f;
    __syncthreads();

    /* -------- phase 1: BN(x) load + edge stash + per-warp dst counts ---- */
    if (t < NPG * FIN) {
        int l = t / FIN, f = t % FIN;
        float v = x[(size_t)band * NNODES * FIN + (size_t)(b*NPG + l) * FIN + f];
        s_xn[l][f] = v * s_bnp[f][0] + s_bnp[f][1];
    }
    {
        const int* sp = ei + (size_t)band * 2 * NE + (size_t)b * EG;
        const int* dp = sp + NE;
        int base = b * NPG;
        for (int e = t; e < NEDG; e += 512) {
            int ls, ld;
            if (e < EG) { ls = sp[e] - base; ld = dp[e] - base; }
            else        { ls = ld = e - EG; }                 /* self loops */
            s_tmp[e] = (unsigned short)(ls | (ld << 8));
            atomicAdd(&s_cntw[w][ld], 1);
        }
    }
    __syncthreads();

    /* -------- phase 2a: per-warp base conversion | xt = xn @ W ---------- */
    if (t < 64) {
        int c = 0;
        #pragma unroll
        for (int ww = 0; ww < 16; ww++) {
            int tmp = s_cntw[ww][t]; s_cntw[ww][t] = c; c += tmp;
        }
        s_cnt[t] = c;
    } else {
        for (int idx = t - 64; idx < NPG * 24; idx += 448) {
            int l = idx / 24, k = idx % 24;
            float acc = s_xn[l][0]*s_W[k]    + s_xn[l][1]*s_W[24+k]
                      + s_xn[l][2]*s_W[48+k] + s_xn[l][3]*s_W[72+k]
                      + s_xn[l][4]*s_W[96+k];
            int h = k / 3, c = k % 3;
            s_xt[l*32 + h*4 + c] = acc;
        }
    }
    __syncthreads();

    /* -------- phase 2b: warp0 scan | others: logits (als into pad) ------ */
    if (w == 0) {
        int c0 = s_cnt[lane], c1 = s_cnt[lane + 32];
        int v0 = c0, v1 = c1;
        #pragma unroll
        for (int o = 1; o < 32; o <<= 1) {
            int n0 = __shfl_up_sync(0xffffffffu, v0, o);
            int n1 = __shfl_up_sync(0xffffffffu, v1, o);
            if (lane >= o) { v0 += n0; v1 += n1; }
        }
        v1 += __shfl_sync(0xffffffffu, v0, 31);
        s_excl[lane]      = v0 - c0;
        s_excl[lane + 32] = v1 - c1;
    } else {
        for (int idx = t - 32; idx < NPG * NH; idx += 480) {
            int l = idx >> 3, h = idx & 7;
            const float* xp = &s_xt[l*32 + h*4];
            float x0 = xp[0], x1 = xp[1], x2 = xp[2];
            s_xt[l*32 + h*4 + 3] = x0*s_as[h*3] + x1*s_as[h*3+1] + x2*s_as[h*3+2];
            s_ald[idx]           = x0*s_ad[h*3] + x1*s_ad[h*3+1] + x2*s_ad[h*3+2];
        }
    }
    __syncthreads();

    /* -------- phase 3: scatter into CSR via per-warp cursors ------------ */
    for (int e = t; e < NEDG; e += 512) {
        unsigned u = s_tmp[e];
        int ld = u >> 8;
        int p = s_excl[ld] + atomicAdd(&s_cntw[w][ld], 1);
        s_srcl[p] = (unsigned char)(u & 0xFF);
    }
    __syncthreads();

    /* -------- phase 4: atomic-free gather per (dst, head) --------------- */
    if (t < NPG * NH) {
        int d = t >> 3, h = t & 7;
        int beg = s_excl[d];
        int end = beg + s_cnt[d];
        float ald = s_ald[t];
        float den = 0.f, a0 = 0.f, a1 = 0.f, a2 = 0.f;
        #pragma unroll 2
        for (int e = beg; e < end; e++) {
            int ls = s_srcl[e];
            const float4 xv = *(const float4*)&s_xt[ls*32 + h*4];  /* x0,x1,x2,als */
            float ev = xv.w + ald;
            ev = fmaxf(ev, 0.2f * ev);                 /* leaky 0.2 */
            float wgt = __expf(ev);                    /* no max-sub needed */
            den += wgt; a0 += wgt*xv.x; a1 += wgt*xv.y; a2 += wgt*xv.z;
        }
        float inv = 0.125f / den;                      /* /denom then head-mean */
        atomicAdd(&s_no[d*4+0], a0*inv);
        atomicAdd(&s_no[d*4+1], a1*inv);
        atomicAdd(&s_no[d*4+2], a2*inv);
    }
    __syncthreads();

    /* -------- phase 5: bias + elu + graph mean-pool --------------------- */
    if (t < NPG * NC) {
        int d = t / 3, c = t % 3;
        float v = s_no[d*4+c] + s_bias[c];
        v = v > 0.f ? v : expm1f(v);
        atomicAdd(&s_pool[c], v);
    }
    __syncthreads();
    if (t < NC) g_xcat[b*15 + band*3 + t] = s_pool[t] * (1.f/62.f);
}

/* == K3: fg-FC + 512x512 attention + final FC + elu (4 rows, 512 thr) ==== */
__global__ __launch_bounds__(512) void k_attn(
    float* __restrict__ out, const float* __restrict__ faW,
    const float* __restrict__ fab, const float* __restrict__ fgW,
    const float* __restrict__ fgb)
{
    __shared__ float s_q[4*64], s_xo[4*64], s_sc[4*512], s_de[4*64];
    __shared__ __align__(16) float s_vt[64][68];     /* V tile, pad 68 */
    __shared__ float s_part[16][4];
    __shared__ float s_inv[4];
    int t = threadIdx.x, rowbase = blockIdx.x * 4;

    /* phase A: fg FC + Q load; idle threads of block 0 reset g_stats */
    if (t < 256) {
        int r = t >> 6, c = t & 63;
        float acc = fgb[c];
        #pragma unroll
        for (int i = 0; i < 15; i++)
            acc += g_xcat[(rowbase+r)*15 + i] * fgW[i*64 + c];
        s_xo[t] = acc > 0.f ? acc : expm1f(acc);
        s_q[t]  = g_Q[(rowbase+r)*64 + c];
    } else if (blockIdx.x == 0 && t < 256 + NB*10) {
        ((float*)g_stats)[t - 256] = 0.f;            /* replay-safe reset */
    }
    __syncthreads();

    /* phase B: scores, one column j per thread, 8-wide load batching */
    float ps[4];
    {
        int j = t;
        float acc[4] = {0.f, 0.f, 0.f, 0.f};
        for (int cb = 0; cb < 64; cb += 8) {
            float kv[8];
            #pragma unroll
            for (int i = 0; i < 8; i++) kv[i] = g_Kt[(cb+i)*BATCH + j];
            #pragma unroll
            for (int i = 0; i < 8; i++) {
                #pragma unroll
                for (int r = 0; r < 4; r++) acc[r] += s_q[r*64 + cb + i] * kv[i];
            }
        }
        #pragma unroll
        for (int r = 0; r < 4; r++) {
            float p = __expf(acc[r] * 0.125f);
            s_sc[r*512 + j] = p;
            ps[r] = p;
        }
    }
    #pragma unroll
    for (int o = 16; o > 0; o >>= 1) {
        #pragma unroll
        for (int r = 0; r < 4; r++) ps[r] += __shfl_xor_sync(0xffffffffu, ps[r], o);
    }
    { int w = t >> 5, lane = t & 31;
      if (lane == 0) { s_part[w][0]=ps[0]; s_part[w][1]=ps[1]; s_part[w][2]=ps[2]; s_part[w][3]=ps[3]; } }
    __syncthreads();
    if (t < 4) {
        float s = 0.f;
        #pragma unroll
        for (int w = 0; w < 16; w++) s += s_part[w][t];
        s_inv[t] = 1.f / s;
    }
    __syncthreads();

    /* phase C: PV via smem V tiles; thread = (r, cg, js), 8-way j-split */
    {
        int r = t >> 7, cg = (t >> 3) & 15, js = t & 7;
        float ax = 0.f, ay = 0.f, az = 0.f, aw = 0.f;
        for (int jt = 0; jt < 8; jt++) {
            int j0 = jt * 64;
            #pragma unroll
            for (int kk = 0; kk < 2; kk++) {
                int idx = t + kk*512;
                int jr = idx >> 4, c4 = idx & 15;
                *(float4*)&s_vt[jr][c4*4] =
                    *(const float4*)&g_V[(size_t)(j0+jr)*64 + c4*4];
            }
            __syncthreads();
            #pragma unroll
            for (int jj = 0; jj < 8; jj++) {
                int jl = jj*8 + js;
                float p = s_sc[r*512 + j0 + jl];
                float4 vv = *(const float4*)&s_vt[jl][cg*4];
                ax += p*vv.x; ay += p*vv.y; az += p*vv.z; aw += p*vv.w;
            }
            __syncthreads();
        }
        #pragma unroll
        for (int o = 1; o <= 4; o <<= 1) {
            ax += __shfl_xor_sync(0xffffffffu, ax, o);
            ay += __shfl_xor_sync(0xffffffffu, ay, o);
            az += __shfl_xor_sync(0xffffffffu, az, o);
            aw += __shfl_xor_sync(0xffffffffu, aw, o);
        }
        if (js == 0) {
            float inv = s_inv[r];
            s_de[r*64 + cg*4 + 0] = ax * inv;
            s_de[r*64 + cg*4 + 1] = ay * inv;
            s_de[r*64 + cg*4 + 2] = az * inv;
            s_de[r*64 + cg*4 + 3] = aw * inv;
        }
    }
    __syncthreads();

    /* phase D: final FC + elu */
    if (t < 12) {
        int r = t / 3, c = t % 3;
        float acc = fab[c];
        #pragma unroll 8
        for (int i = 0; i < 64; i++) {
            acc += s_xo[r*64 + i] * faW[i*3 + c];
            acc += s_de[r*64 + i] * faW[(64+i)*3 + c];
        }
        acc = acc > 0.f ? acc : expm1f(acc);
        out[(rowbase+r)*3 + c] = acc;
    }
}

/* ============================== launcher ================================ */
extern "C" void kernel_launch(void* const* d_in, const int* in_sizes, int n_in,
                              void* d_out, int out_size)
{
    const float* x     = (const float*)d_in[0];
    const int*   ei    = (const int*)  d_in[1];
    const float* de    = (const float*)d_in[3];
    const float* bng   = (const float*)d_in[4];
    const float* bnb   = (const float*)d_in[5];
    const float* W     = (const float*)d_in[6];
    const float* asrc  = (const float*)d_in[7];
    const float* adst  = (const float*)d_in[8];
    const float* gbias = (const float*)d_in[9];
    const float* fgW   = (const float*)d_in[10];
    const float* fgb   = (const float*)d_in[11];
    const float* lng   = (const float*)d_in[12];
    const float* lnb   = (const float*)d_in[13];
    const float* qW    = (const float*)d_in[14];
    const float* qb    = (const float*)d_in[15];
    const float* kW    = (const float*)d_in[16];
    const float* kb    = (const float*)d_in[17];
    const float* vW    = (const float*)d_in[18];
    const float* vb    = (const float*)d_in[19];
    const float* faW   = (const float*)d_in[20];
    const float* fab   = (const float*)d_in[21];
    float* out = (float*)d_out;

    /* strictly sequential, default stream — capture-safe */
    k_fused<<<312, 512>>>(de, lng, lnb, qW, qb, kW, kb, vW, vb, x);
    k_gat<<<dim3(BATCH, NB), 512>>>(x, ei, W, asrc, adst, gbias, bng, bnb);
    k_attn<<<128, 512>>>(out, faW, fab, fgW, fgb);
}

// round 11
// speedup vs baseline: 2.0159x; 1.0099x over previous
#include <cuda_runtime.h>

#define NB    5
#define BATCH 512
#define NPG   62
#define NNODES (BATCH*NPG)      /* 31744 */
#define FIN   5
#define NH    8
#define NC    3
#define EG    992               /* edges per graph */
#define NE    (BATCH*EG)        /* 507904 edges per band */
#define NEDG  (EG+NPG)          /* 1054 incl self loops */
#define DED   930
#define KCH   117               /* ceil(930/8) k-chunks of 8 */

/* ---------------- device scratch (no allocations allowed) ---------------- */
__device__ float g_stats[NB][10];                 /* zero-init; re-zeroed by k_attn */
__device__ __align__(16) float g_xcat[BATCH*15];
__device__ __align__(16) float g_Q[BATCH*64];
__device__ __align__(16) float g_Kt[64*BATCH];    /* transposed K */
__device__ __align__(16) float g_V[BATCH*64];
__device__ __align__(16) unsigned char g_srcl[(size_t)NB*BATCH*1056]; /* CSR src */
__device__ int g_excl[NB*BATCH*64];               /* CSR offsets */

/* == K1: fused QKV-GEMM (0..191) + BN stats (192..311) + edge sort (rest) = */
struct GemmSmem {
    float sN[8][948];                              /* normalized A rows, padded */
    union {
        float sW[8][8][64];                        /* [split][kk][col]   */
        float sAcc[8][8][68];                      /* [split][row][col]  */
    } u;
};
struct SortSmem {
    unsigned short s_tmp[NEDG];
    __align__(16) unsigned char s_srcl[1056];
    int s_cntw[16][64];
    int s_excl[64];
};

__global__ __launch_bounds__(512) void k_fused(
    const float* __restrict__ de,  const float* __restrict__ lng,
    const float* __restrict__ lnb,
    const float* __restrict__ qW,  const float* __restrict__ qb,
    const float* __restrict__ kW,  const float* __restrict__ kb,
    const float* __restrict__ vW,  const float* __restrict__ vb,
    const float* __restrict__ x,   const int* __restrict__ ei)
{
    __shared__ union { GemmSmem g; SortSmem s; float red[16][10]; } S;
    int bid = blockIdx.x;
    int t = threadIdx.x, w = t >> 5, lane = t & 31;

    if (bid < 192) {
        /* ---------------- QKV GEMM with inline LayerNorm ---------------- */
        int mat = bid / 64, tile = bid % 64;
        int row0 = tile * 8;
        const float* Wm = (mat == 0) ? qW : (mat == 1) ? kW : vW;
        const float* bm = (mat == 0) ? qb : (mat == 1) ? kb : vb;

        /* LN: warp per row (warps 0..7) */
        if (w < 8) {
            const float* dr = de + (size_t)(row0 + w) * DED;
            float v[30];
            float ssum = 0.f, ssq = 0.f;
            #pragma unroll
            for (int i = 0; i < 30; i++) {
                int j = lane + i*32;
                float z = (j < DED) ? dr[j] : 0.f;
                v[i] = z; ssum += z; ssq += z*z;
            }
            #pragma unroll
            for (int o = 16; o > 0; o >>= 1) {
                ssum += __shfl_xor_sync(0xffffffffu, ssum, o);
                ssq  += __shfl_xor_sync(0xffffffffu, ssq, o);
            }
            float mu   = ssum * (1.f/DED);
            float rstd = rsqrtf(ssq * (1.f/DED) - mu*mu + 1e-5f);
            #pragma unroll
            for (int i = 0; i < 30; i++) {
                int j = lane + i*32;
                if (j < DED) S.g.sN[w][j] = (v[i] - mu) * rstd * lng[j] + lnb[j];
            }
            for (int j = DED + lane; j < 948; j += 32) S.g.sN[w][j] = 0.f;
        }
        __syncthreads();

        int s  = t >> 6;          /* split 0..7 (64-thread group)   */
        int u  = t & 63;
        int rg = u >> 4;          /* rows rg*2, rg*2+1              */
        int cg = u & 15;          /* cols cg*4 .. +3                */

        float a0c0=0.f,a0c1=0.f,a0c2=0.f,a0c3=0.f;
        float a1c0=0.f,a1c1=0.f,a1c2=0.f,a1c3=0.f;

        /* register prefetch of first W chunk */
        float4 p0, p1;
        {
            int k0 = s * 8;
            int kA = k0 + rg, kB = k0 + rg + 4;
            p0 = (kA < DED) ? *(const float4*)(Wm + (size_t)kA*64 + cg*4)
                            : make_float4(0.f,0.f,0.f,0.f);
            p1 = (kB < DED) ? *(const float4*)(Wm + (size_t)kB*64 + cg*4)
                            : make_float4(0.f,0.f,0.f,0.f);
        }
        for (int kc = s; kc < KCH; kc += 8) {
            int k0 = kc * 8;
            *(float4*)&S.g.u.sW[s][rg  ][cg*4] = p0;
            *(float4*)&S.g.u.sW[s][rg+4][cg*4] = p1;
            asm volatile("bar.sync %0, 64;" :: "r"(s+1) : "memory");
            if (kc + 8 < KCH) {       /* prefetch next chunk, overlaps FMAs */
                int kn = (kc + 8) * 8;
                int kA = kn + rg, kB = kn + rg + 4;
                p0 = (kA < DED) ? *(const float4*)(Wm + (size_t)kA*64 + cg*4)
                                : make_float4(0.f,0.f,0.f,0.f);
                p1 = (kB < DED) ? *(const float4*)(Wm + (size_t)kB*64 + cg*4)
                                : make_float4(0.f,0.f,0.f,0.f);
            }
            #pragma unroll
            for (int kk = 0; kk < 8; kk++) {
                float a0 = S.g.sN[rg*2  ][k0+kk];
                float a1 = S.g.sN[rg*2+1][k0+kk];
                float4 wv = *(const float4*)&S.g.u.sW[s][kk][cg*4];
                a0c0 += a0*wv.x; a0c1 += a0*wv.y; a0c2 += a0*wv.z; a0c3 += a0*wv.w;
                a1c0 += a1*wv.x; a1c1 += a1*wv.y; a1c2 += a1*wv.z; a1c3 += a1*wv.w;
            }
            asm volatile("bar.sync %0, 64;" :: "r"(s+1) : "memory");
        }
        __syncthreads();                 /* sW region reused as sAcc */
        *(float4*)&S.g.u.sAcc[s][rg*2  ][cg*4] = make_float4(a0c0,a0c1,a0c2,a0c3);
        *(float4*)&S.g.u.sAcc[s][rg*2+1][cg*4] = make_float4(a1c0,a1c1,a1c2,a1c3);
        __syncthreads();

        int r = t >> 6, c = t & 63;
        float v = bm[c];
        #pragma unroll
        for (int ss = 0; ss < 8; ss++) v += S.g.u.sAcc[ss][r][c];
        if (mat == 1) g_Kt[(size_t)c * BATCH + row0 + r] = v;
        else {
            float* dst = (mat == 0) ? g_Q : g_V;
            dst[(size_t)(row0 + r) * 64 + c] = v;
        }
    } else if (bid < 312) {
        /* ---------------- BN statistics (120 blocks) -------------------- */
        int idx = bid - 192;
        int band = idx / 24, slice = idx % 24;
        const float* xb = x + (size_t)band * NNODES * FIN;
        float sm[5] = {0,0,0,0,0}, q[5] = {0,0,0,0,0};
        for (int n = slice * 512 + t; n < NNODES; n += 24 * 512) {
            const float* p = xb + (size_t)n * FIN;
            #pragma unroll
            for (int f = 0; f < 5; f++) { float v = p[f]; sm[f] += v; q[f] += v*v; }
        }
        #pragma unroll
        for (int o = 16; o > 0; o >>= 1) {
            #pragma unroll
            for (int f = 0; f < 5; f++) {
                sm[f] += __shfl_xor_sync(0xffffffffu, sm[f], o);
                q[f]  += __shfl_xor_sync(0xffffffffu, q[f],  o);
            }
        }
        if (lane == 0) {
            #pragma unroll
            for (int f = 0; f < 5; f++) { S.red[w][f] = sm[f]; S.red[w][5+f] = q[f]; }
        }
        __syncthreads();
        if (t < 10) {
            float acc = 0.f;
            #pragma unroll
            for (int i = 0; i < 16; i++) acc += S.red[i][t];
            atomicAdd(&g_stats[band][t], acc);
        }
    } else {
        /* ---------------- edge sort → CSR (2560 blocks) ----------------- */
        int idx = bid - 312;
        int band = idx / BATCH, b = idx % BATCH;
        for (int i = t; i < 16*64; i += 512) ((int*)S.s.s_cntw)[i] = 0;
        __syncthreads();
        const int* sp = ei + (size_t)band * 2 * NE + (size_t)b * EG;
        const int* dp = sp + NE;
        int base = b * NPG;
        for (int e = t; e < NEDG; e += 512) {
            int ls, ld;
            if (e < EG) { ls = sp[e] - base; ld = dp[e] - base; }
            else        { ls = ld = e - EG; }                 /* self loops */
            S.s.s_tmp[e] = (unsigned short)(ls | (ld << 8));
            atomicAdd(&S.s.s_cntw[w][ld], 1);
        }
        __syncthreads();
        if (w == 0) {     /* per-warp base conversion + scan, one warp */
            int c0 = 0, c1 = 0;
            #pragma unroll
            for (int ww = 0; ww < 16; ww++) {
                int t0 = S.s.s_cntw[ww][lane];    S.s.s_cntw[ww][lane]    = c0; c0 += t0;
                int t1 = S.s.s_cntw[ww][lane+32]; S.s.s_cntw[ww][lane+32] = c1; c1 += t1;
            }
            int v0 = c0, v1 = c1;
            #pragma unroll
            for (int o = 1; o < 32; o <<= 1) {
                int n0 = __shfl_up_sync(0xffffffffu, v0, o);
                int n1 = __shfl_up_sync(0xffffffffu, v1, o);
                if (lane >= o) { v0 += n0; v1 += n1; }
            }
            v1 += __shfl_sync(0xffffffffu, v0, 31);
            S.s.s_excl[lane]      = v0 - c0;
            S.s.s_excl[lane + 32] = v1 - c1;
        }
        __syncthreads();
        for (int e = t; e < NEDG; e += 512) {
            unsigned u = S.s.s_tmp[e];
            int ld = u >> 8;
            int p = S.s.s_excl[ld] + atomicAdd(&S.s.s_cntw[w][ld], 1);
            S.s.s_srcl[p] = (unsigned char)(u & 0xFF);
        }
        __syncthreads();
        size_t ob = (size_t)(band * BATCH + b);
        if (t < 66)
            ((uint4*)(g_srcl + ob*1056))[t] = ((const uint4*)S.s.s_srcl)[t];
        else if (t < 130)
            g_excl[ob*64 + (t - 66)] = S.s.s_excl[t - 66];
    }
}

/* ====== K2: per-(band,graph) GAT + pooling (CSR precomputed) ============ */
__global__ __launch_bounds__(512) void k_gat(
    const float* __restrict__ x,
    const float* __restrict__ W, const float* __restrict__ asrc,
    const float* __restrict__ adst, const float* __restrict__ gbias,
    const float* __restrict__ bng, const float* __restrict__ bnb)
{
    int b = blockIdx.x, band = blockIdx.y;
    int t = threadIdx.x;

    __shared__ float s_xn[NPG][FIN];                 /* raw x */
    __shared__ __align__(16) float s_xt[NPG*NH*4];   /* [l][h]{x0,x1,x2,als} */
    __shared__ float s_ald[NPG*NH];
    __shared__ __align__(16) unsigned char s_srcl[1056];
    __shared__ int s_excl[65];
    __shared__ float s_Wp[FIN*24], s_shW[24], s_as[24], s_ad[24], s_bias[NC];
    __shared__ float s_no[NPG*4];
    __shared__ float s_pool[NC];

    /* -------- phase 0: CSR + params (BN folded into weights) + raw x ---- */
    size_t ob = (size_t)(band * BATCH + b);
    if (t < 66) {
        ((uint4*)s_srcl)[t] = ((const uint4*)(g_srcl + ob*1056))[t];
    } else if (t < 131) {
        int d = t - 66;
        s_excl[d] = (d < 64) ? g_excl[ob*64 + d] : NEDG;
    } else if (t < 155) {
        int k = t - 131;
        float sh = 0.f;
        #pragma unroll
        for (int f = 0; f < FIN; f++) {
            float mean = g_stats[band][f] * (1.f/NNODES);
            float var  = g_stats[band][5+f] * (1.f/NNODES) - mean*mean;
            float sc   = rsqrtf(var + 1e-5f) * bng[band*5+f];
            float shf  = bnb[band*5+f] - mean*sc;
            float wv   = W[band*120 + f*24 + k];
            s_Wp[f*24 + k] = wv * sc;
            sh += wv * shf;
        }
        s_shW[k] = sh;
    }
    else if (t < 179) s_as[t-155] = asrc[band*24 + (t-155)];
    else if (t < 203) s_ad[t-179] = adst[band*24 + (t-179)];
    else if (t < 206) { s_bias[t-203] = gbias[band*3 + (t-203)]; s_pool[t-203] = 0.f; }
    if (t < NPG*4) s_no[t] = 0.f;
    if (t >= 202) {                                  /* 310 threads: raw x */
        int i = t - 202;
        int l = i / FIN, f = i % FIN;
        s_xn[l][f] = x[(size_t)band * NNODES * FIN + (size_t)(b*NPG + l) * FIN + f];
    }
    __syncthreads();

    /* -------- phase 1: xt = (x*sc+sh) @ W via folded weights ------------ */
    for (int idx = t; idx < NPG * 24; idx += 512) {
        int l = idx / 24, k = idx % 24;
        float acc = s_shW[k]
                  + s_xn[l][0]*s_Wp[k]    + s_xn[l][1]*s_Wp[24+k]
                  + s_xn[l][2]*s_Wp[48+k] + s_xn[l][3]*s_Wp[72+k]
                  + s_xn[l][4]*s_Wp[96+k];
        int h = k / 3, c = k % 3;
        s_xt[l*32 + h*4 + c] = acc;
    }
    __syncthreads();

    /* -------- phase 2: attention logits (als into float4 pad) ----------- */
    if (t < NPG * NH) {
        int l = t >> 3, h = t & 7;
        const float* xp = &s_xt[l*32 + h*4];
        float x0 = xp[0], x1 = xp[1], x2 = xp[2];
        s_xt[l*32 + h*4 + 3] = x0*s_as[h*3] + x1*s_as[h*3+1] + x2*s_as[h*3+2];
        s_ald[t]             = x0*s_ad[h*3] + x1*s_ad[h*3+1] + x2*s_ad[h*3+2];
    }
    __syncthreads();

    /* -------- phase 3: atomic-free gather per (dst, head) --------------- */
    if (t < NPG * NH) {
        int d = t >> 3, h = t & 7;
        int beg = s_excl[d], end = s_excl[d+1];
        float ald = s_ald[t];
        float den = 0.f, a0 = 0.f, a1 = 0.f, a2 = 0.f;
        #pragma unroll 2
        for (int e = beg; e < end; e++) {
            int ls = s_srcl[e];
            const float4 xv = *(const float4*)&s_xt[ls*32 + h*4];  /* x0,x1,x2,als */
            float ev = xv.w + ald;
            ev = fmaxf(ev, 0.2f * ev);                 /* leaky 0.2 */
            float wgt = __expf(ev);                    /* no max-sub needed */
            den += wgt; a0 += wgt*xv.x; a1 += wgt*xv.y; a2 += wgt*xv.z;
        }
        float inv = 0.125f / den;                      /* /denom then head-mean */
        atomicAdd(&s_no[d*4+0], a0*inv);
        atomicAdd(&s_no[d*4+1], a1*inv);
        atomicAdd(&s_no[d*4+2], a2*inv);
    }
    __syncthreads();

    /* -------- phase 4: bias + elu + graph mean-pool --------------------- */
    if (t < NPG * NC) {
        int d = t / 3, c = t % 3;
        float v = s_no[d*4+c] + s_bias[c];
        v = v > 0.f ? v : expm1f(v);
        atomicAdd(&s_pool[c], v);
    }
    __syncthreads();
    if (t < NC) g_xcat[b*15 + band*3 + t] = s_pool[t] * (1.f/62.f);
}

/* == K3: fg-FC + 512x512 attention + final FC + elu (4 rows, 512 thr) ==== */
__global__ __launch_bounds__(512) void k_attn(
    float* __restrict__ out, const float* __restrict__ faW,
    const float* __restrict__ fab, const float* __restrict__ fgW,
    const float* __restrict__ fgb)
{
    __shared__ float s_q[4*64], s_xo[4*64], s_sc[4*512], s_de[4*64];
    __shared__ __align__(16) float s_vt[64][68];     /* V tile, pad 68 */
    __shared__ float s_part[16][4];
    __shared__ float s_inv[4];
    int t = threadIdx.x, rowbase = blockIdx.x * 4;

    /* phase A: fg FC + Q load; idle threads of block 0 reset g_stats */
    if (t < 256) {
        int r = t >> 6, c = t & 63;
        float acc = fgb[c];
        #pragma unroll
        for (int i = 0; i < 15; i++)
            acc += g_xcat[(rowbase+r)*15 + i] * fgW[i*64 + c];
        s_xo[t] = acc > 0.f ? acc : expm1f(acc);
        s_q[t]  = g_Q[(rowbase+r)*64 + c];
    } else if (blockIdx.x == 0 && t < 256 + NB*10) {
        ((float*)g_stats)[t - 256] = 0.f;            /* replay-safe reset */
    }
    __syncthreads();

    /* phase B: scores, one column j per thread, 8-wide load batching */
    float ps[4];
    {
        int j = t;
        float acc[4] = {0.f, 0.f, 0.f, 0.f};
        for (int cb = 0; cb < 64; cb += 8) {
            float kv[8];
            #pragma unroll
            for (int i = 0; i < 8; i++) kv[i] = g_Kt[(cb+i)*BATCH + j];
            #pragma unroll
            for (int i = 0; i < 8; i++) {
                #pragma unroll
                for (int r = 0; r < 4; r++) acc[r] += s_q[r*64 + cb + i] * kv[i];
            }
        }
        #pragma unroll
        for (int r = 0; r < 4; r++) {
            float p = __expf(acc[r] * 0.125f);
            s_sc[r*512 + j] = p;
            ps[r] = p;
        }
    }
    #pragma unroll
    for (int o = 16; o > 0; o >>= 1) {
        #pragma unroll
        for (int r = 0; r < 4; r++) ps[r] += __shfl_xor_sync(0xffffffffu, ps[r], o);
    }
    { int w = t >> 5, lane = t & 31;
      if (lane == 0) { s_part[w][0]=ps[0]; s_part[w][1]=ps[1]; s_part[w][2]=ps[2]; s_part[w][3]=ps[3]; } }
    __syncthreads();
    if (t < 4) {
        float s = 0.f;
        #pragma unroll
        for (int w = 0; w < 16; w++) s += s_part[w][t];
        s_inv[t] = 1.f / s;
    }
    __syncthreads();

    /* phase C: PV via smem V tiles; thread = (r, cg, js), 8-way j-split */
    {
        int r = t >> 7, cg = (t >> 3) & 15, js = t & 7;
        float ax = 0.f, ay = 0.f, az = 0.f, aw = 0.f;
        for (int jt = 0; jt < 8; jt++) {
            int j0 = jt * 64;
            #pragma unroll
            for (int kk = 0; kk < 2; kk++) {
                int idx = t + kk*512;
                int jr = idx >> 4, c4 = idx & 15;
                *(float4*)&s_vt[jr][c4*4] =
                    *(const float4*)&g_V[(size_t)(j0+jr)*64 + c4*4];
            }
            __syncthreads();
            #pragma unroll
            for (int jj = 0; jj < 8; jj++) {
                int jl = jj*8 + js;
                float p = s_sc[r*512 + j0 + jl];
                float4 vv = *(const float4*)&s_vt[jl][cg*4];
                ax += p*vv.x; ay += p*vv.y; az += p*vv.z; aw += p*vv.w;
            }
            __syncthreads();
        }
        #pragma unroll
        for (int o = 1; o <= 4; o <<= 1) {
            ax += __shfl_xor_sync(0xffffffffu, ax, o);
            ay += __shfl_xor_sync(0xffffffffu, ay, o);
            az += __shfl_xor_sync(0xffffffffu, az, o);
            aw += __shfl_xor_sync(0xffffffffu, aw, o);
        }
        if (js == 0) {
            float inv = s_inv[r];
            s_de[r*64 + cg*4 + 0] = ax * inv;
            s_de[r*64 + cg*4 + 1] = ay * inv;
            s_de[r*64 + cg*4 + 2] = az * inv;
            s_de[r*64 + cg*4 + 3] = aw * inv;
        }
    }
    __syncthreads();

    /* phase D: final FC + elu */
    if (t < 12) {
        int r = t / 3, c = t % 3;
        float acc = fab[c];
        #pragma unroll 8
        for (int i = 0; i < 64; i++) {
            acc += s_xo[r*64 + i] * faW[i*3 + c];
            acc += s_de[r*64 + i] * faW[(64+i)*3 + c];
        }
        acc = acc > 0.f ? acc : expm1f(acc);
        out[(rowbase+r)*3 + c] = acc;
    }
}

/* ============================== launcher ================================ */
extern "C" void kernel_launch(void* const* d_in, const int* in_sizes, int n_in,
                              void* d_out, int out_size)
{
    const float* x     = (const float*)d_in[0];
    const int*   ei    = (const int*)  d_in[1];
    const float* de    = (const float*)d_in[3];
    const float* bng   = (const float*)d_in[4];
    const float* bnb   = (const float*)d_in[5];
    const float* W     = (const float*)d_in[6];
    const float* asrc  = (const float*)d_in[7];
    const float* adst  = (const float*)d_in[8];
    const float* gbias = (const float*)d_in[9];
    const float* fgW   = (const float*)d_in[10];
    const float* fgb   = (const float*)d_in[11];
    const float* lng   = (const float*)d_in[12];
    const float* lnb   = (const float*)d_in[13];
    const float* qW    = (const float*)d_in[14];
    const float* qb    = (const float*)d_in[15];
    const float* kW    = (const float*)d_in[16];
    const float* kb    = (const float*)d_in[17];
    const float* vW    = (const float*)d_in[18];
    const float* vb    = (const float*)d_in[19];
    const float* faW   = (const float*)d_in[20];
    const float* fab   = (const float*)d_in[21];
    float* out = (float*)d_out;

    /* strictly sequential, default stream — capture-safe */
    k_fused<<<312 + NB*BATCH, 512>>>(de, lng, lnb, qW, qb, kW, kb, vW, vb, x, ei);
    k_gat<<<dim3(BATCH, NB), 512>>>(x, W, asrc, adst, gbias, bng, bnb);
    k_attn<<<128, 512>>>(out, faW, fab, fgW, fgb);
}